// round 1
// baseline (speedup 1.0000x reference)
#include <cuda_runtime.h>
#include <math.h>

#define N_NODES   8192
#define N_EDGES   16384
#define N_GRAPHS  256
#define N_STEMS   2048
#define N_JBONDS  1024
#define DIM       64
#define NUM_FEAT  14
#define NUM_OUT   105

// ---------------- scratch (device globals; no allocations allowed) ----------------
__device__ float g_ew[(size_t)N_EDGES * DIM * DIM];   // 256 MiB edge-conditioned weights
__device__ float g_h1[N_EDGES * DIM];                 // edge-net hidden
__device__ float g_h[N_NODES * DIM];                  // node state (out == h)
__device__ float g_agg[N_NODES * DIM];                // scatter accumulator
__device__ float g_deg[N_NODES];
__device__ float g_q[DIM];

__device__ __forceinline__ float lrelu(float v) { return v > 0.f ? v : 0.01f * v; }
__device__ __forceinline__ float sigm(float v)  { return 1.f / (1.f + expf(-v)); }
__device__ __forceinline__ void fma4(float4& a, float s, const float4 v) {
    a.x += s * v.x; a.y += s * v.y; a.z += s * v.z; a.w += s * v.w;
}

// ---------------- degree ----------------
__global__ void zero_deg_kernel() {
    g_deg[blockIdx.x * 256 + threadIdx.x] = 0.f;
}
__global__ void deg_kernel(const int* __restrict__ dst) {
    int e = blockIdx.x * 256 + threadIdx.x;
    if (e < N_EDGES) atomicAdd(&g_deg[dst[e]], 1.0f);
}
__global__ void zero_agg_kernel() {
    int i = blockIdx.x * 256 + threadIdx.x;
    ((float4*)g_agg)[i] = make_float4(0.f, 0.f, 0.f, 0.f);
}

// ---------------- lin0: h = lrelu(x @ W + b) ----------------
__global__ void lin0_kernel(const float* __restrict__ x,
                            const float* __restrict__ W,
                            const float* __restrict__ b) {
    int tid = blockIdx.x * 256 + threadIdx.x;
    int n = tid >> 6, o = tid & 63;
    float acc = b[o];
#pragma unroll
    for (int i = 0; i < NUM_FEAT; i++) acc += x[n * NUM_FEAT + i] * W[i * DIM + o];
    g_h[(size_t)n * DIM + o] = lrelu(acc);
}

// ---------------- edge net hidden: h1 = lrelu(ea @ W1 + b1) ----------------
__global__ void h1_kernel(const float* __restrict__ ea,
                          const float* __restrict__ W1,
                          const float* __restrict__ b1) {
    int tid = blockIdx.x * 256 + threadIdx.x;
    int e = tid >> 6, k = tid & 63;
    float acc = b1[k];
#pragma unroll
    for (int i = 0; i < 4; i++) acc += ea[e * 4 + i] * W1[i * DIM + k];
    g_h1[(size_t)e * DIM + k] = lrelu(acc);
}

// ---------------- ew = h1 @ W2 + b2   (GEMM 16384x4096x64, fp32) ----------------
// 128x128 tile, K-chunk 32, 256 threads, 8x8 per thread.
__global__ __launch_bounds__(256) void ew_gemm_kernel(const float* __restrict__ B,
                                                      const float* __restrict__ bias) {
    __shared__ float As[32][132];   // transposed A tile, padded (16B-aligned rows)
    __shared__ float Bs[32][128];
    int bn = blockIdx.x * 128;
    int bm = blockIdx.y * 128;
    int tid = threadIdx.x;
    int tx = tid & 15, ty = tid >> 4;
    float acc[8][8];
#pragma unroll
    for (int i = 0; i < 8; i++)
#pragma unroll
        for (int j = 0; j < 8; j++) acc[i][j] = 0.f;

    for (int kk = 0; kk < 64; kk += 32) {
#pragma unroll
        for (int i = 0; i < 4; i++) {
            int idx = tid + i * 256;          // float4 index over 128x32 A tile
            int row = idx >> 3, c4 = idx & 7;
            float4 v = *(const float4*)&g_h1[(size_t)(bm + row) * 64 + kk + c4 * 4];
            As[c4 * 4 + 0][row] = v.x; As[c4 * 4 + 1][row] = v.y;
            As[c4 * 4 + 2][row] = v.z; As[c4 * 4 + 3][row] = v.w;
        }
#pragma unroll
        for (int i = 0; i < 4; i++) {
            int idx = tid + i * 256;          // float4 index over 32x128 B tile
            int r = idx >> 5, c4 = idx & 31;
            *(float4*)&Bs[r][c4 * 4] = *(const float4*)&B[(size_t)(kk + r) * 4096 + bn + c4 * 4];
        }
        __syncthreads();
#pragma unroll
        for (int k = 0; k < 32; k++) {
            float a[8], bb[8];
            float4 a0 = *(const float4*)&As[k][ty * 8];
            float4 a1 = *(const float4*)&As[k][ty * 8 + 4];
            float4 b0 = *(const float4*)&Bs[k][tx * 8];
            float4 b1v = *(const float4*)&Bs[k][tx * 8 + 4];
            a[0]=a0.x;a[1]=a0.y;a[2]=a0.z;a[3]=a0.w;a[4]=a1.x;a[5]=a1.y;a[6]=a1.z;a[7]=a1.w;
            bb[0]=b0.x;bb[1]=b0.y;bb[2]=b0.z;bb[3]=b0.w;bb[4]=b1v.x;bb[5]=b1v.y;bb[6]=b1v.z;bb[7]=b1v.w;
#pragma unroll
            for (int i = 0; i < 8; i++)
#pragma unroll
                for (int j = 0; j < 8; j++) acc[i][j] += a[i] * bb[j];
        }
        __syncthreads();
    }
#pragma unroll
    for (int i = 0; i < 8; i++) {
        size_t crow = (size_t)(bm + ty * 8 + i) * 4096 + bn;
#pragma unroll
        for (int j4 = 0; j4 < 2; j4++) {
            int c = tx * 8 + j4 * 4;
            float4 o;
            o.x = acc[i][j4 * 4 + 0] + bias[bn + c + 0];
            o.y = acc[i][j4 * 4 + 1] + bias[bn + c + 1];
            o.z = acc[i][j4 * 4 + 2] + bias[bn + c + 2];
            o.w = acc[i][j4 * 4 + 3] + bias[bn + c + 3];
            *(float4*)&g_ew[crow + c] = o;
        }
    }
}

// ---------------- msg: agg[dst] += h[src] @ ew[e]   (8 edges/block) ----------------
__global__ __launch_bounds__(128) void msg_kernel(const int* __restrict__ src,
                                                  const int* __restrict__ dst) {
    __shared__ float hs[8][64];
    int tid = threadIdx.x;
    int slot = tid >> 4, t16 = tid & 15;
    int e = blockIdx.x * 8 + slot;
    int s = src[e];
    *(float4*)&hs[slot][t16 * 4] = *(const float4*)&g_h[(size_t)s * 64 + t16 * 4];
    __syncthreads();
    float4 acc = make_float4(0.f, 0.f, 0.f, 0.f);
    const float4* ewp = (const float4*)(g_ew + (size_t)e * 4096);
#pragma unroll 8
    for (int i = 0; i < 64; i++) {
        float hv = hs[slot][i];
        float4 w = ewp[i * 16 + t16];
        acc.x += hv * w.x; acc.y += hv * w.y; acc.z += hv * w.z; acc.w += hv * w.w;
    }
    int d = dst[e];
    float* ap = &g_agg[(size_t)d * 64 + t16 * 4];
    atomicAdd(ap + 0, acc.x); atomicAdd(ap + 1, acc.y);
    atomicAdd(ap + 2, acc.z); atomicAdd(ap + 3, acc.w);
}

// ---------------- fused NNConv epilogue + GRU (64 nodes/block) ----------------
__global__ __launch_bounds__(256) void node_update_kernel(
    const float* __restrict__ R, const float* __restrict__ cbias,
    const float* __restrict__ Wih, const float* __restrict__ Whh,
    const float* __restrict__ bih, const float* __restrict__ bhh) {
    __shared__ float hsm[64][64];
    __shared__ float msm[64][64];
    int n0 = blockIdx.x * 64;
    int tid = threadIdx.x;
#pragma unroll
    for (int i = 0; i < 4; i++) {
        int idx = tid + i * 256;
        int row = idx >> 4, c4 = idx & 15;
        *(float4*)&hsm[row][c4 * 4] = *(const float4*)&g_h[(size_t)(n0 + row) * 64 + c4 * 4];
    }
    __syncthreads();
    int tx = tid & 15, ty = tid >> 4;

    // phase B: m = lrelu(agg/deg + h @ R + cbias)
    {
        float4 accm[4] = {};
#pragma unroll 8
        for (int i = 0; i < 64; i++) {
            float4 r4 = *(const float4*)&R[i * 64 + tx * 4];
#pragma unroll
            for (int j = 0; j < 4; j++) fma4(accm[j], hsm[ty * 4 + j][i], r4);
        }
        float4 cb4 = *(const float4*)&cbias[tx * 4];
#pragma unroll
        for (int j = 0; j < 4; j++) {
            int n = n0 + ty * 4 + j;
            float inv = 1.0f / fmaxf(g_deg[n], 1.0f);
            float4 ag = *(const float4*)&g_agg[(size_t)n * 64 + tx * 4];
            float4 m;
            m.x = lrelu(ag.x * inv + accm[j].x + cb4.x);
            m.y = lrelu(ag.y * inv + accm[j].y + cb4.y);
            m.z = lrelu(ag.z * inv + accm[j].z + cb4.z);
            m.w = lrelu(ag.w * inv + accm[j].w + cb4.w);
            *(float4*)&msm[ty * 4 + j][tx * 4] = m;
        }
    }
    __syncthreads();

    // phase C: GRU gates (r,z,n) for 4 nodes x 4 dims per thread
    float4 gir[4] = {}, giz[4] = {}, gin[4] = {}, ghr[4] = {}, ghz[4] = {}, ghn[4] = {};
#pragma unroll 4
    for (int i = 0; i < 64; i++) {
        const float* wi = &Wih[i * 192 + tx * 4];
        const float* wh = &Whh[i * 192 + tx * 4];
        float4 wir = *(const float4*)(wi);
        float4 wiz = *(const float4*)(wi + 64);
        float4 win = *(const float4*)(wi + 128);
        float4 whr = *(const float4*)(wh);
        float4 whz = *(const float4*)(wh + 64);
        float4 whn = *(const float4*)(wh + 128);
#pragma unroll
        for (int j = 0; j < 4; j++) {
            float mv = msm[ty * 4 + j][i];
            float hv = hsm[ty * 4 + j][i];
            fma4(gir[j], mv, wir); fma4(giz[j], mv, wiz); fma4(gin[j], mv, win);
            fma4(ghr[j], hv, whr); fma4(ghz[j], hv, whz); fma4(ghn[j], hv, whn);
        }
    }
    float4 bir = *(const float4*)&bih[tx * 4];
    float4 biz = *(const float4*)&bih[64 + tx * 4];
    float4 bin = *(const float4*)&bih[128 + tx * 4];
    float4 bhr = *(const float4*)&bhh[tx * 4];
    float4 bhz = *(const float4*)&bhh[64 + tx * 4];
    float4 bhn = *(const float4*)&bhh[128 + tx * 4];
#pragma unroll
    for (int j = 0; j < 4; j++) {
        int n = n0 + ty * 4 + j;
        float4 hold = *(float4*)&hsm[ty * 4 + j][tx * 4];
        float4 hn;
        {
            float r = sigm(gir[j].x + bir.x + ghr[j].x + bhr.x);
            float z = sigm(giz[j].x + biz.x + ghz[j].x + bhz.x);
            float nn = tanhf(gin[j].x + bin.x + r * (ghn[j].x + bhn.x));
            hn.x = (1.f - z) * nn + z * hold.x;
        }
        {
            float r = sigm(gir[j].y + bir.y + ghr[j].y + bhr.y);
            float z = sigm(giz[j].y + biz.y + ghz[j].y + bhz.y);
            float nn = tanhf(gin[j].y + bin.y + r * (ghn[j].y + bhn.y));
            hn.y = (1.f - z) * nn + z * hold.y;
        }
        {
            float r = sigm(gir[j].z + bir.z + ghr[j].z + bhr.z);
            float z = sigm(giz[j].z + biz.z + ghz[j].z + bhz.z);
            float nn = tanhf(gin[j].z + bin.z + r * (ghn[j].z + bhn.z));
            hn.z = (1.f - z) * nn + z * hold.z;
        }
        {
            float r = sigm(gir[j].w + bir.w + ghr[j].w + bhr.w);
            float z = sigm(giz[j].w + biz.w + ghz[j].w + bhz.w);
            float nn = tanhf(gin[j].w + bin.w + r * (ghn[j].w + bhn.w));
            hn.w = (1.f - z) * nn + z * hold.w;
        }
        *(float4*)&g_h[(size_t)n * 64 + tx * 4] = hn;
    }
}

// ---------------- stem head ----------------
__global__ __launch_bounds__(128) void stem_kernel(const int* __restrict__ idx,
                                                   const float* __restrict__ W1, const float* __restrict__ b1,
                                                   const float* __restrict__ W2, const float* __restrict__ b2,
                                                   float* __restrict__ outp) {
    __shared__ float row[64], hid[64];
    int s = blockIdx.x, t = threadIdx.x;
    int atom = idx[s];
    if (t < 64) row[t] = g_h[(size_t)atom * 64 + t];
    __syncthreads();
    if (t < 64) {
        float acc = b1[t];
#pragma unroll
        for (int i = 0; i < 64; i++) acc += row[i] * W1[i * 64 + t];
        hid[t] = lrelu(acc);
    }
    __syncthreads();
    for (int o = t; o < NUM_OUT; o += 128) {
        float acc = b2[o];
#pragma unroll
        for (int i = 0; i < 64; i++) acc += hid[i] * W2[i * NUM_OUT + o];
        outp[512 + (size_t)s * NUM_OUT + o] = acc;
    }
}

// ---------------- jbond head ----------------
__global__ __launch_bounds__(128) void jbond_kernel(const int* __restrict__ idx,
                                                    const float* __restrict__ W1, const float* __restrict__ b1,
                                                    const float* __restrict__ w2, const float* __restrict__ b2,
                                                    float* __restrict__ outp) {
    __shared__ float row[2][64];
    __shared__ float warpsum[4];
    int jb = blockIdx.x, t = threadIdx.x;
    int a = t >> 6, tt = t & 63;
    int atom = idx[jb * 2 + a];
    row[a][tt] = g_h[(size_t)atom * 64 + tt];
    __syncthreads();
    float acc = b1[tt];
#pragma unroll
    for (int i = 0; i < 64; i++) acc += row[a][i] * W1[i * 64 + tt];
    float p = lrelu(acc) * w2[tt];
#pragma unroll
    for (int off = 16; off; off >>= 1) p += __shfl_xor_sync(0xffffffffu, p, off);
    if ((t & 31) == 0) warpsum[t >> 5] = p;
    __syncthreads();
    if (t == 0) {
        float p0 = warpsum[0] + warpsum[1] + b2[0];
        float p1 = warpsum[2] + warpsum[3] + b2[0];
        outp[512 + (size_t)N_STEMS * NUM_OUT + jb] = 0.5f * (p0 + p1);
    }
}

// ---------------- Set2Set q (bias-only; identical for all graphs) ----------------
__global__ void s2s_q_kernel(const float* __restrict__ bih, const float* __restrict__ bhh) {
    int d = threadIdx.x;
    float bi = bih[d]       + bhh[d];
    float bg = bih[128 + d] + bhh[128 + d];
    float bo = bih[192 + d] + bhh[192 + d];
    float c = sigm(bi) * tanhf(bg);            // sigmoid(f)*c0 term is zero
    g_q[d] = sigm(bo) * tanhf(c);
}

// ---------------- per-graph attention pool + lin_out ----------------
__global__ __launch_bounds__(128) void pool_kernel(const int* __restrict__ batch,
                                                   const float* __restrict__ W, const float* __restrict__ bias,
                                                   float* __restrict__ outp) {
    __shared__ int s_lo, s_hi;
    __shared__ float s_max[4], s_ws[4], s_pool[4][64], s_r[64];
    int b = blockIdx.x, t = threadIdx.x;
    if (t == 0) {
        int lo = 0, hi = N_NODES;
        while (lo < hi) { int m = (lo + hi) >> 1; if (batch[m] < b) lo = m + 1; else hi = m; }
        s_lo = lo;
        int lo2 = lo, hi2 = N_NODES;
        while (lo2 < hi2) { int m = (lo2 + hi2) >> 1; if (batch[m] < b + 1) lo2 = m + 1; else hi2 = m; }
        s_hi = lo2;
    }
    __syncthreads();
    int lo = s_lo, hi = s_hi;
    int warp = t >> 5, lane = t & 31;
    float q0 = g_q[lane], q1 = g_q[32 + lane];
    float lmax = -3.4e38f;
    for (int n = lo + warp; n < hi; n += 4) {
        float v = g_h[(size_t)n * 64 + lane] * q0 + g_h[(size_t)n * 64 + 32 + lane] * q1;
#pragma unroll
        for (int off = 16; off; off >>= 1) v += __shfl_xor_sync(0xffffffffu, v, off);
        lmax = fmaxf(lmax, v);
    }
    if (lane == 0) s_max[warp] = lmax;
    __syncthreads();
    float emax = fmaxf(fmaxf(s_max[0], s_max[1]), fmaxf(s_max[2], s_max[3]));
    float p0 = 0.f, p1 = 0.f, ws = 0.f;
    for (int n = lo + warp; n < hi; n += 4) {
        float h0 = g_h[(size_t)n * 64 + lane], h1v = g_h[(size_t)n * 64 + 32 + lane];
        float v = h0 * q0 + h1v * q1;
#pragma unroll
        for (int off = 16; off; off >>= 1) v += __shfl_xor_sync(0xffffffffu, v, off);
        float c = expf(v - emax);
        p0 += c * h0; p1 += c * h1v; ws += c;
    }
    s_pool[warp][lane] = p0; s_pool[warp][32 + lane] = p1;
    if (lane == 0) s_ws[warp] = ws;
    __syncthreads();
    if (t < 64) {
        float ps = s_pool[0][t] + s_pool[1][t] + s_pool[2][t] + s_pool[3][t];
        float wtot = s_ws[0] + s_ws[1] + s_ws[2] + s_ws[3];
        s_r[t] = (wtot > 0.f) ? ps / wtot : 0.f;
    }
    __syncthreads();
    if (t < 2) {
        float acc = bias[t];
        for (int d = 0; d < 64; d++)
            acc += g_q[d] * W[d * 2 + t] + s_r[d] * W[(64 + d) * 2 + t];
        outp[b * 2 + t] = acc;
    }
}

// ---------------- launch ----------------
extern "C" void kernel_launch(void* const* d_in, const int* in_sizes, int n_in,
                              void* d_out, int out_size) {
    const float* x          = (const float*)d_in[0];
    const float* edge_attr  = (const float*)d_in[1];
    const int*   edge_index = (const int*)  d_in[2];
    const int*   batch      = (const int*)  d_in[3];
    const int*   stem_idx   = (const int*)  d_in[4];
    const int*   jbond_idx  = (const int*)  d_in[5];
    const float* lin0_w   = (const float*)d_in[6];
    const float* lin0_b   = (const float*)d_in[7];
    const float* net_w1   = (const float*)d_in[8];
    const float* net_b1   = (const float*)d_in[9];
    const float* net_w2   = (const float*)d_in[10];
    const float* net_b2   = (const float*)d_in[11];
    const float* conv_root= (const float*)d_in[12];
    const float* conv_bias= (const float*)d_in[13];
    const float* gru_w_ih = (const float*)d_in[14];
    const float* gru_w_hh = (const float*)d_in[15];
    const float* gru_b_ih = (const float*)d_in[16];
    const float* gru_b_hh = (const float*)d_in[17];
    const float* n2s_w1   = (const float*)d_in[18];
    const float* n2s_b1   = (const float*)d_in[19];
    const float* n2s_w2   = (const float*)d_in[20];
    const float* n2s_b2   = (const float*)d_in[21];
    const float* n2j_w1   = (const float*)d_in[22];
    const float* n2j_b1   = (const float*)d_in[23];
    const float* n2j_w2   = (const float*)d_in[24];
    const float* n2j_b2   = (const float*)d_in[25];
    const float* s2s_b_ih = (const float*)d_in[28];
    const float* s2s_b_hh = (const float*)d_in[29];
    const float* lin_out_w= (const float*)d_in[30];
    const float* lin_out_b= (const float*)d_in[31];
    float* out = (float*)d_out;

    const int* src = edge_index;             // edge_index[0]
    const int* dst = edge_index + N_EDGES;   // edge_index[1]

    zero_deg_kernel<<<N_NODES / 256, 256>>>();
    deg_kernel<<<(N_EDGES + 255) / 256, 256>>>(dst);
    lin0_kernel<<<N_NODES * DIM / 256, 256>>>(x, lin0_w, lin0_b);
    h1_kernel<<<N_EDGES * DIM / 256, 256>>>(edge_attr, net_w1, net_b1);
    ew_gemm_kernel<<<dim3(4096 / 128, N_EDGES / 128), 256>>>(net_w2, net_b2);

    for (int it = 0; it < 6; it++) {
        zero_agg_kernel<<<N_NODES * DIM / 4 / 256, 256>>>();
        msg_kernel<<<N_EDGES / 8, 128>>>(src, dst);
        node_update_kernel<<<N_NODES / 64, 256>>>(conv_root, conv_bias,
                                                  gru_w_ih, gru_w_hh, gru_b_ih, gru_b_hh);
    }

    stem_kernel<<<N_STEMS, 128>>>(stem_idx, n2s_w1, n2s_b1, n2s_w2, n2s_b2, out);
    jbond_kernel<<<N_JBONDS, 128>>>(jbond_idx, n2j_w1, n2j_b1, n2j_w2, n2j_b2, out);
    s2s_q_kernel<<<1, 64>>>(s2s_b_ih, s2s_b_hh);
    pool_kernel<<<N_GRAPHS, 128>>>(batch, lin_out_w, lin_out_b, out);
}

// round 3
// speedup vs baseline: 1.5923x; 1.5923x over previous
#include <cuda_runtime.h>
#include <cuda_bf16.h>
#include <cstdint>
#include <math.h>

#define N_NODES   8192
#define N_EDGES   16384
#define N_GRAPHS  256
#define N_STEMS   2048
#define N_JBONDS  1024
#define DIM       64
#define NUM_FEAT  14
#define NUM_OUT   105

// ---------------- scratch (device globals; no allocations allowed) ----------------
__device__ __nv_bfloat16 g_ewb[(size_t)N_EDGES * DIM * DIM]; // 128 MiB bf16 edge weights
__device__ __nv_bfloat16 g_h1b[N_EDGES * DIM];               // edge-net hidden (bf16)
__device__ __nv_bfloat16 g_w2t[4096 * 64];                   // W2 transposed [4096][64] bf16
__device__ float g_h[N_NODES * DIM];                         // node state
__device__ float g_agg[N_NODES * DIM];                       // scatter accumulator
__device__ float g_deg[N_NODES];
__device__ float g_q[DIM];

__device__ __forceinline__ float lrelu(float v) { return v > 0.f ? v : 0.01f * v; }
__device__ __forceinline__ float sigm(float v)  { return 1.f / (1.f + expf(-v)); }
__device__ __forceinline__ void fma4(float4& a, float s, const float4 v) {
    a.x += s * v.x; a.y += s * v.y; a.z += s * v.z; a.w += s * v.w;
}

// ---------------- degree ----------------
__global__ void zero_deg_kernel() {
    g_deg[blockIdx.x * 256 + threadIdx.x] = 0.f;
}
__global__ void deg_kernel(const int* __restrict__ dst) {
    int e = blockIdx.x * 256 + threadIdx.x;
    if (e < N_EDGES) atomicAdd(&g_deg[dst[e]], 1.0f);
}
__global__ void zero_agg_kernel() {
    int i = blockIdx.x * 256 + threadIdx.x;
    ((float4*)g_agg)[i] = make_float4(0.f, 0.f, 0.f, 0.f);
}

// ---------------- lin0: h = lrelu(x @ W + b) ----------------
__global__ void lin0_kernel(const float* __restrict__ x,
                            const float* __restrict__ W,
                            const float* __restrict__ b) {
    int tid = blockIdx.x * 256 + threadIdx.x;
    int n = tid >> 6, o = tid & 63;
    float acc = b[o];
#pragma unroll
    for (int i = 0; i < NUM_FEAT; i++) acc += x[n * NUM_FEAT + i] * W[i * DIM + o];
    g_h[(size_t)n * DIM + o] = lrelu(acc);
}

// ---------------- edge net hidden: h1 = lrelu(ea @ W1 + b1), bf16 store ----------------
__global__ void h1_kernel(const float* __restrict__ ea,
                          const float* __restrict__ W1,
                          const float* __restrict__ b1) {
    int tid = blockIdx.x * 256 + threadIdx.x;
    int e = tid >> 6, k = tid & 63;
    float acc = b1[k];
#pragma unroll
    for (int i = 0; i < 4; i++) acc += ea[e * 4 + i] * W1[i * DIM + k];
    g_h1b[(size_t)e * DIM + k] = __float2bfloat16(lrelu(acc));
}

// ---------------- W2 transpose to bf16: W2t[n][k] = W2[k][n] ----------------
__global__ void w2t_kernel(const float* __restrict__ W2) {
    int idx = blockIdx.x * 256 + threadIdx.x;   // idx = k*4096 + n (coalesced read)
    int k = idx >> 12, n = idx & 4095;
    g_w2t[n * 64 + k] = __float2bfloat16(W2[idx]);
}

// ---------------- ew = h1 @ W2 + b2 via tensor cores (bf16 in, fp32 acc, bf16 out) ----
// M=16384, N=4096, K=64. Block 128x128, 8 warps, warp tile 64x32 (4x m16, 4x n8).
__global__ __launch_bounds__(256) void ew_gemm_tc(const float* __restrict__ bias) {
    __shared__ __nv_bfloat16 As[128][72];
    __shared__ __nv_bfloat16 Bs[128][72];
    int bm = blockIdx.y * 128, bn = blockIdx.x * 128;
    int tid = threadIdx.x;

#pragma unroll
    for (int p = 0; p < 4; p++) {
        int idx = tid + p * 256;
        int row = idx >> 3, c8 = (idx & 7) * 8;
        *(uint4*)&As[row][c8] = *(const uint4*)&g_h1b[(size_t)(bm + row) * 64 + c8];
        *(uint4*)&Bs[row][c8] = *(const uint4*)&g_w2t[(size_t)(bn + row) * 64 + c8];
    }
    __syncthreads();

    int w = tid >> 5, lane = tid & 31;
    int wm = (w >> 2) * 64, wn = (w & 3) * 32;
    int g = lane >> 2, t4 = lane & 3;

    float c[4][4][4];
#pragma unroll
    for (int mi = 0; mi < 4; mi++)
#pragma unroll
        for (int ni = 0; ni < 4; ni++)
#pragma unroll
            for (int r = 0; r < 4; r++) c[mi][ni][r] = 0.f;

#pragma unroll
    for (int ks = 0; ks < 4; ks++) {
        int k0 = ks * 16;
        uint32_t a[4][4], b[4][2];
#pragma unroll
        for (int mi = 0; mi < 4; mi++) {
            int r0 = wm + mi * 16 + g;
            a[mi][0] = *(const uint32_t*)&As[r0][k0 + 2 * t4];
            a[mi][1] = *(const uint32_t*)&As[r0 + 8][k0 + 2 * t4];
            a[mi][2] = *(const uint32_t*)&As[r0][k0 + 2 * t4 + 8];
            a[mi][3] = *(const uint32_t*)&As[r0 + 8][k0 + 2 * t4 + 8];
        }
#pragma unroll
        for (int ni = 0; ni < 4; ni++) {
            int nr = wn + ni * 8 + g;
            b[ni][0] = *(const uint32_t*)&Bs[nr][k0 + 2 * t4];
            b[ni][1] = *(const uint32_t*)&Bs[nr][k0 + 2 * t4 + 8];
        }
#pragma unroll
        for (int mi = 0; mi < 4; mi++)
#pragma unroll
            for (int ni = 0; ni < 4; ni++) {
                asm volatile(
                    "mma.sync.aligned.m16n8k16.row.col.f32.bf16.bf16.f32 "
                    "{%0,%1,%2,%3}, {%4,%5,%6,%7}, {%8,%9}, {%0,%1,%2,%3};"
                    : "+f"(c[mi][ni][0]), "+f"(c[mi][ni][1]),
                      "+f"(c[mi][ni][2]), "+f"(c[mi][ni][3])
                    : "r"(a[mi][0]), "r"(a[mi][1]), "r"(a[mi][2]), "r"(a[mi][3]),
                      "r"(b[ni][0]), "r"(b[ni][1]));
            }
    }

#pragma unroll
    for (int mi = 0; mi < 4; mi++) {
        int row0 = bm + wm + mi * 16 + g;
#pragma unroll
        for (int ni = 0; ni < 4; ni++) {
            int n = bn + wn + ni * 8 + 2 * t4;
            float b0 = bias[n], b1v = bias[n + 1];
            __nv_bfloat162 v0 = __floats2bfloat162_rn(c[mi][ni][0] + b0, c[mi][ni][1] + b1v);
            __nv_bfloat162 v1 = __floats2bfloat162_rn(c[mi][ni][2] + b0, c[mi][ni][3] + b1v);
            *reinterpret_cast<__nv_bfloat162*>(&g_ewb[(size_t)row0 * 4096 + n]) = v0;
            *reinterpret_cast<__nv_bfloat162*>(&g_ewb[(size_t)(row0 + 8) * 4096 + n]) = v1;
        }
    }
}

// ---------------- msg: agg[dst] += h[src] @ ew[e]   (bf16 weights, 8 edges/block) ----
__global__ __launch_bounds__(128) void msg_kernel(const int* __restrict__ src,
                                                  const int* __restrict__ dst) {
    __shared__ float hs[8][64];
    int tid = threadIdx.x;
    int slot = tid >> 4, t16 = tid & 15;
    int e = blockIdx.x * 8 + slot;
    int s = src[e];
    *(float4*)&hs[slot][t16 * 4] = *(const float4*)&g_h[(size_t)s * 64 + t16 * 4];
    __syncthreads();
    float4 acc = make_float4(0.f, 0.f, 0.f, 0.f);
    const uint2* ewp = reinterpret_cast<const uint2*>(g_ewb + (size_t)e * 4096 + t16 * 4);
#pragma unroll 8
    for (int i = 0; i < 64; i++) {
        float hv = hs[slot][i];
        uint2 raw = ewp[i * 16];
        float2 w01 = __bfloat1622float2(*reinterpret_cast<__nv_bfloat162*>(&raw.x));
        float2 w23 = __bfloat1622float2(*reinterpret_cast<__nv_bfloat162*>(&raw.y));
        acc.x += hv * w01.x; acc.y += hv * w01.y;
        acc.z += hv * w23.x; acc.w += hv * w23.y;
    }
    int d = dst[e];
    float* ap = &g_agg[(size_t)d * 64 + t16 * 4];
    atomicAdd(ap + 0, acc.x); atomicAdd(ap + 1, acc.y);
    atomicAdd(ap + 2, acc.z); atomicAdd(ap + 3, acc.w);
}

// ---------------- fused NNConv epilogue + GRU (64 nodes/block) ----------------
__global__ __launch_bounds__(256) void node_update_kernel(
    const float* __restrict__ R, const float* __restrict__ cbias,
    const float* __restrict__ Wih, const float* __restrict__ Whh,
    const float* __restrict__ bih, const float* __restrict__ bhh) {
    __shared__ float hsm[64][64];
    __shared__ float msm[64][64];
    int n0 = blockIdx.x * 64;
    int tid = threadIdx.x;
#pragma unroll
    for (int i = 0; i < 4; i++) {
        int idx = tid + i * 256;
        int row = idx >> 4, c4 = idx & 15;
        *(float4*)&hsm[row][c4 * 4] = *(const float4*)&g_h[(size_t)(n0 + row) * 64 + c4 * 4];
    }
    __syncthreads();
    int tx = tid & 15, ty = tid >> 4;

    // phase B: m = lrelu(agg/deg + h @ R + cbias)
    {
        float4 accm[4] = {};
#pragma unroll 8
        for (int i = 0; i < 64; i++) {
            float4 r4 = *(const float4*)&R[i * 64 + tx * 4];
#pragma unroll
            for (int j = 0; j < 4; j++) fma4(accm[j], hsm[ty * 4 + j][i], r4);
        }
        float4 cb4 = *(const float4*)&cbias[tx * 4];
#pragma unroll
        for (int j = 0; j < 4; j++) {
            int n = n0 + ty * 4 + j;
            float inv = 1.0f / fmaxf(g_deg[n], 1.0f);
            float4 ag = *(const float4*)&g_agg[(size_t)n * 64 + tx * 4];
            float4 m;
            m.x = lrelu(ag.x * inv + accm[j].x + cb4.x);
            m.y = lrelu(ag.y * inv + accm[j].y + cb4.y);
            m.z = lrelu(ag.z * inv + accm[j].z + cb4.z);
            m.w = lrelu(ag.w * inv + accm[j].w + cb4.w);
            *(float4*)&msm[ty * 4 + j][tx * 4] = m;
        }
    }
    __syncthreads();

    // phase C: GRU gates (r,z,n)
    float4 gir[4] = {}, giz[4] = {}, gin[4] = {}, ghr[4] = {}, ghz[4] = {}, ghn[4] = {};
#pragma unroll 4
    for (int i = 0; i < 64; i++) {
        const float* wi = &Wih[i * 192 + tx * 4];
        const float* wh = &Whh[i * 192 + tx * 4];
        float4 wir = *(const float4*)(wi);
        float4 wiz = *(const float4*)(wi + 64);
        float4 win = *(const float4*)(wi + 128);
        float4 whr = *(const float4*)(wh);
        float4 whz = *(const float4*)(wh + 64);
        float4 whn = *(const float4*)(wh + 128);
#pragma unroll
        for (int j = 0; j < 4; j++) {
            float mv = msm[ty * 4 + j][i];
            float hv = hsm[ty * 4 + j][i];
            fma4(gir[j], mv, wir); fma4(giz[j], mv, wiz); fma4(gin[j], mv, win);
            fma4(ghr[j], hv, whr); fma4(ghz[j], hv, whz); fma4(ghn[j], hv, whn);
        }
    }
    float4 bir = *(const float4*)&bih[tx * 4];
    float4 biz = *(const float4*)&bih[64 + tx * 4];
    float4 bin = *(const float4*)&bih[128 + tx * 4];
    float4 bhr = *(const float4*)&bhh[tx * 4];
    float4 bhz = *(const float4*)&bhh[64 + tx * 4];
    float4 bhn = *(const float4*)&bhh[128 + tx * 4];
#pragma unroll
    for (int j = 0; j < 4; j++) {
        int n = n0 + ty * 4 + j;
        float4 hold = *(float4*)&hsm[ty * 4 + j][tx * 4];
        float4 hn;
        {
            float r = sigm(gir[j].x + bir.x + ghr[j].x + bhr.x);
            float z = sigm(giz[j].x + biz.x + ghz[j].x + bhz.x);
            float nn = tanhf(gin[j].x + bin.x + r * (ghn[j].x + bhn.x));
            hn.x = (1.f - z) * nn + z * hold.x;
        }
        {
            float r = sigm(gir[j].y + bir.y + ghr[j].y + bhr.y);
            float z = sigm(giz[j].y + biz.y + ghz[j].y + bhz.y);
            float nn = tanhf(gin[j].y + bin.y + r * (ghn[j].y + bhn.y));
            hn.y = (1.f - z) * nn + z * hold.y;
        }
        {
            float r = sigm(gir[j].z + bir.z + ghr[j].z + bhr.z);
            float z = sigm(giz[j].z + biz.z + ghz[j].z + bhz.z);
            float nn = tanhf(gin[j].z + bin.z + r * (ghn[j].z + bhn.z));
            hn.z = (1.f - z) * nn + z * hold.z;
        }
        {
            float r = sigm(gir[j].w + bir.w + ghr[j].w + bhr.w);
            float z = sigm(giz[j].w + biz.w + ghz[j].w + bhz.w);
            float nn = tanhf(gin[j].w + bin.w + r * (ghn[j].w + bhn.w));
            hn.w = (1.f - z) * nn + z * hold.w;
        }
        *(float4*)&g_h[(size_t)n * 64 + tx * 4] = hn;
    }
}

// ---------------- stem head ----------------
__global__ __launch_bounds__(128) void stem_kernel(const int* __restrict__ idx,
                                                   const float* __restrict__ W1, const float* __restrict__ b1,
                                                   const float* __restrict__ W2, const float* __restrict__ b2,
                                                   float* __restrict__ outp) {
    __shared__ float row[64], hid[64];
    int s = blockIdx.x, t = threadIdx.x;
    int atom = idx[s];
    if (t < 64) row[t] = g_h[(size_t)atom * 64 + t];
    __syncthreads();
    if (t < 64) {
        float acc = b1[t];
#pragma unroll
        for (int i = 0; i < 64; i++) acc += row[i] * W1[i * 64 + t];
        hid[t] = lrelu(acc);
    }
    __syncthreads();
    for (int o = t; o < NUM_OUT; o += 128) {
        float acc = b2[o];
#pragma unroll
        for (int i = 0; i < 64; i++) acc += hid[i] * W2[i * NUM_OUT + o];
        outp[512 + (size_t)s * NUM_OUT + o] = acc;
    }
}

// ---------------- jbond head ----------------
__global__ __launch_bounds__(128) void jbond_kernel(const int* __restrict__ idx,
                                                    const float* __restrict__ W1, const float* __restrict__ b1,
                                                    const float* __restrict__ w2, const float* __restrict__ b2,
                                                    float* __restrict__ outp) {
    __shared__ float row[2][64];
    __shared__ float warpsum[4];
    int jb = blockIdx.x, t = threadIdx.x;
    int a = t >> 6, tt = t & 63;
    int atom = idx[jb * 2 + a];
    row[a][tt] = g_h[(size_t)atom * 64 + tt];
    __syncthreads();
    float acc = b1[tt];
#pragma unroll
    for (int i = 0; i < 64; i++) acc += row[a][i] * W1[i * 64 + tt];
    float p = lrelu(acc) * w2[tt];
#pragma unroll
    for (int off = 16; off; off >>= 1) p += __shfl_xor_sync(0xffffffffu, p, off);
    if ((t & 31) == 0) warpsum[t >> 5] = p;
    __syncthreads();
    if (t == 0) {
        float p0 = warpsum[0] + warpsum[1] + b2[0];
        float p1 = warpsum[2] + warpsum[3] + b2[0];
        outp[512 + (size_t)N_STEMS * NUM_OUT + jb] = 0.5f * (p0 + p1);
    }
}

// ---------------- Set2Set q (bias-only; identical for all graphs) ----------------
__global__ void s2s_q_kernel(const float* __restrict__ bih, const float* __restrict__ bhh) {
    int d = threadIdx.x;
    float bi = bih[d]       + bhh[d];
    float bg = bih[128 + d] + bhh[128 + d];
    float bo = bih[192 + d] + bhh[192 + d];
    float c = sigm(bi) * tanhf(bg);
    g_q[d] = sigm(bo) * tanhf(c);
}

// ---------------- per-graph attention pool + lin_out ----------------
__global__ __launch_bounds__(128) void pool_kernel(const int* __restrict__ batch,
                                                   const float* __restrict__ W, const float* __restrict__ bias,
                                                   float* __restrict__ outp) {
    __shared__ int s_lo, s_hi;
    __shared__ float s_max[4], s_ws[4], s_pool[4][64], s_r[64];
    int b = blockIdx.x, t = threadIdx.x;
    if (t == 0) {
        int lo = 0, hi = N_NODES;
        while (lo < hi) { int m = (lo + hi) >> 1; if (batch[m] < b) lo = m + 1; else hi = m; }
        s_lo = lo;
        int lo2 = lo, hi2 = N_NODES;
        while (lo2 < hi2) { int m = (lo2 + hi2) >> 1; if (batch[m] < b + 1) lo2 = m + 1; else hi2 = m; }
        s_hi = lo2;
    }
    __syncthreads();
    int lo = s_lo, hi = s_hi;
    int warp = t >> 5, lane = t & 31;
    float q0 = g_q[lane], q1 = g_q[32 + lane];
    float lmax = -3.4e38f;
    for (int n = lo + warp; n < hi; n += 4) {
        float v = g_h[(size_t)n * 64 + lane] * q0 + g_h[(size_t)n * 64 + 32 + lane] * q1;
#pragma unroll
        for (int off = 16; off; off >>= 1) v += __shfl_xor_sync(0xffffffffu, v, off);
        lmax = fmaxf(lmax, v);
    }
    if (lane == 0) s_max[warp] = lmax;
    __syncthreads();
    float emax = fmaxf(fmaxf(s_max[0], s_max[1]), fmaxf(s_max[2], s_max[3]));
    float p0 = 0.f, p1 = 0.f, ws = 0.f;
    for (int n = lo + warp; n < hi; n += 4) {
        float h0 = g_h[(size_t)n * 64 + lane], h1v = g_h[(size_t)n * 64 + 32 + lane];
        float v = h0 * q0 + h1v * q1;
#pragma unroll
        for (int off = 16; off; off >>= 1) v += __shfl_xor_sync(0xffffffffu, v, off);
        float c = expf(v - emax);
        p0 += c * h0; p1 += c * h1v; ws += c;
    }
    s_pool[warp][lane] = p0; s_pool[warp][32 + lane] = p1;
    if (lane == 0) s_ws[warp] = ws;
    __syncthreads();
    if (t < 64) {
        float ps = s_pool[0][t] + s_pool[1][t] + s_pool[2][t] + s_pool[3][t];
        float wtot = s_ws[0] + s_ws[1] + s_ws[2] + s_ws[3];
        s_r[t] = (wtot > 0.f) ? ps / wtot : 0.f;
    }
    __syncthreads();
    if (t < 2) {
        float acc = bias[t];
        for (int d = 0; d < 64; d++)
            acc += g_q[d] * W[d * 2 + t] + s_r[d] * W[(64 + d) * 2 + t];
        outp[b * 2 + t] = acc;
    }
}

// ---------------- launch ----------------
extern "C" void kernel_launch(void* const* d_in, const int* in_sizes, int n_in,
                              void* d_out, int out_size) {
    const float* x          = (const float*)d_in[0];
    const float* edge_attr  = (const float*)d_in[1];
    const int*   edge_index = (const int*)  d_in[2];
    const int*   batch      = (const int*)  d_in[3];
    const int*   stem_idx   = (const int*)  d_in[4];
    const int*   jbond_idx  = (const int*)  d_in[5];
    const float* lin0_w   = (const float*)d_in[6];
    const float* lin0_b   = (const float*)d_in[7];
    const float* net_w1   = (const float*)d_in[8];
    const float* net_b1   = (const float*)d_in[9];
    const float* net_w2   = (const float*)d_in[10];
    const float* net_b2   = (const float*)d_in[11];
    const float* conv_root= (const float*)d_in[12];
    const float* conv_bias= (const float*)d_in[13];
    const float* gru_w_ih = (const float*)d_in[14];
    const float* gru_w_hh = (const float*)d_in[15];
    const float* gru_b_ih = (const float*)d_in[16];
    const float* gru_b_hh = (const float*)d_in[17];
    const float* n2s_w1   = (const float*)d_in[18];
    const float* n2s_b1   = (const float*)d_in[19];
    const float* n2s_w2   = (const float*)d_in[20];
    const float* n2s_b2   = (const float*)d_in[21];
    const float* n2j_w1   = (const float*)d_in[22];
    const float* n2j_b1   = (const float*)d_in[23];
    const float* n2j_w2   = (const float*)d_in[24];
    const float* n2j_b2   = (const float*)d_in[25];
    const float* s2s_b_ih = (const float*)d_in[28];
    const float* s2s_b_hh = (const float*)d_in[29];
    const float* lin_out_w= (const float*)d_in[30];
    const float* lin_out_b= (const float*)d_in[31];
    float* out = (float*)d_out;

    const int* src = edge_index;             // edge_index[0]
    const int* dst = edge_index + N_EDGES;   // edge_index[1]

    zero_deg_kernel<<<N_NODES / 256, 256>>>();
    deg_kernel<<<(N_EDGES + 255) / 256, 256>>>(dst);
    lin0_kernel<<<N_NODES * DIM / 256, 256>>>(x, lin0_w, lin0_b);
    h1_kernel<<<N_EDGES * DIM / 256, 256>>>(edge_attr, net_w1, net_b1);
    w2t_kernel<<<DIM * 4096 / 256, 256>>>(net_w2);
    ew_gemm_tc<<<dim3(4096 / 128, N_EDGES / 128), 256>>>(net_b2);

    for (int it = 0; it < 6; it++) {
        zero_agg_kernel<<<N_NODES * DIM / 4 / 256, 256>>>();
        msg_kernel<<<N_EDGES / 8, 128>>>(src, dst);
        node_update_kernel<<<N_NODES / 64, 256>>>(conv_root, conv_bias,
                                                  gru_w_ih, gru_w_hh, gru_b_ih, gru_b_hh);
    }

    stem_kernel<<<N_STEMS, 128>>>(stem_idx, n2s_w1, n2s_b1, n2s_w2, n2s_b2, out);
    jbond_kernel<<<N_JBONDS, 128>>>(jbond_idx, n2j_w1, n2j_b1, n2j_w2, n2j_b2, out);
    s2s_q_kernel<<<1, 64>>>(s2s_b_ih, s2s_b_hh);
    pool_kernel<<<N_GRAPHS, 128>>>(batch, lin_out_w, lin_out_b, out);
}

// round 5
// speedup vs baseline: 2.0326x; 1.2765x over previous
#include <cuda_runtime.h>
#include <cuda_bf16.h>
#include <cstdint>
#include <math.h>

#define N_NODES   8192
#define N_EDGES   16384
#define N_GRAPHS  256
#define N_STEMS   2048
#define N_JBONDS  1024
#define DIM       64
#define NUM_FEAT  14
#define NUM_OUT   105

// ---------------- scratch (device globals; no allocations allowed) ----------------
__device__ __nv_bfloat16 g_ewb[(size_t)N_EDGES * DIM * DIM]; // 128 MiB bf16 edge weights
__device__ __nv_bfloat16 g_h1b[N_EDGES * DIM];               // edge-net hidden (bf16)
__device__ __nv_bfloat16 g_w2t[4096 * 64];                   // W2 transposed [4096][64] bf16
__device__ float g_rt[64 * 64];                              // conv_root^T [o][i] fp32
__device__ float g_wihT[192 * 64];                           // gru_w_ih^T [o][i] fp32
__device__ float g_whhT[192 * 64];                           // gru_w_hh^T [o][i] fp32
__device__ float g_h[N_NODES * DIM];                         // node state
__device__ float g_agg[N_NODES * DIM];                       // scatter accumulator
__device__ float g_deg[N_NODES];                             // becomes 1/max(deg,1)
__device__ float g_q[DIM];

__device__ __forceinline__ float lrelu(float v) { return v > 0.f ? v : 0.01f * v; }
__device__ __forceinline__ float sigm(float v)  { return 1.f / (1.f + expf(-v)); }

__device__ __forceinline__ void mma_bf16(float* c, const uint32_t* a, const uint32_t* b) {
    asm volatile(
        "mma.sync.aligned.m16n8k16.row.col.f32.bf16.bf16.f32 "
        "{%0,%1,%2,%3}, {%4,%5,%6,%7}, {%8,%9}, {%0,%1,%2,%3};"
        : "+f"(c[0]), "+f"(c[1]), "+f"(c[2]), "+f"(c[3])
        : "r"(a[0]), "r"(a[1]), "r"(a[2]), "r"(a[3]), "r"(b[0]), "r"(b[1]));
}

__device__ __forceinline__ uint32_t f2tf32(float f) {
    uint32_t r;
    asm("cvt.rna.tf32.f32 %0, %1;" : "=r"(r) : "f"(f));
    return r;
}

__device__ __forceinline__ void mma_tf32(float* c, const uint32_t* a, const uint32_t* b) {
    asm volatile(
        "mma.sync.aligned.m16n8k8.row.col.f32.tf32.tf32.f32 "
        "{%0,%1,%2,%3}, {%4,%5,%6,%7}, {%8,%9}, {%0,%1,%2,%3};"
        : "+f"(c[0]), "+f"(c[1]), "+f"(c[2]), "+f"(c[3])
        : "r"(a[0]), "r"(a[1]), "r"(a[2]), "r"(a[3]), "r"(b[0]), "r"(b[1]));
}

// ---------------- degree ----------------
__global__ void zero_deg_kernel() {
    g_deg[blockIdx.x * 256 + threadIdx.x] = 0.f;
}
__global__ void deg_kernel(const int* __restrict__ dst) {
    int e = blockIdx.x * 256 + threadIdx.x;
    if (e < N_EDGES) atomicAdd(&g_deg[dst[e]], 1.0f);
}
__global__ void invdeg_kernel() {
    int i = blockIdx.x * 256 + threadIdx.x;
    g_deg[i] = 1.0f / fmaxf(g_deg[i], 1.0f);
}
__global__ void zero_agg_kernel() {
    int i = blockIdx.x * 256 + threadIdx.x;
    ((float4*)g_agg)[i] = make_float4(0.f, 0.f, 0.f, 0.f);
}

// ---------------- lin0: h = lrelu(x @ W + b) ----------------
__global__ void lin0_kernel(const float* __restrict__ x,
                            const float* __restrict__ W,
                            const float* __restrict__ b) {
    int tid = blockIdx.x * 256 + threadIdx.x;
    int n = tid >> 6, o = tid & 63;
    float acc = b[o];
#pragma unroll
    for (int i = 0; i < NUM_FEAT; i++) acc += x[n * NUM_FEAT + i] * W[i * DIM + o];
    g_h[(size_t)n * DIM + o] = lrelu(acc);
}

// ---------------- edge net hidden: h1 = lrelu(ea @ W1 + b1), bf16 store ----------------
__global__ void h1_kernel(const float* __restrict__ ea,
                          const float* __restrict__ W1,
                          const float* __restrict__ b1) {
    int tid = blockIdx.x * 256 + threadIdx.x;
    int e = tid >> 6, k = tid & 63;
    float acc = b1[k];
#pragma unroll
    for (int i = 0; i < 4; i++) acc += ea[e * 4 + i] * W1[i * DIM + k];
    g_h1b[(size_t)e * DIM + k] = __float2bfloat16(lrelu(acc));
}

// ---------------- W2 transpose to bf16 ----------------
__global__ void w2t_kernel(const float* __restrict__ W2) {
    int idx = blockIdx.x * 256 + threadIdx.x;   // idx = k*4096 + n (coalesced read)
    int k = idx >> 12, n = idx & 4095;
    g_w2t[n * 64 + k] = __float2bfloat16(W2[idx]);
}

// ---------------- GRU/root weights -> transposed fp32 ----------------
__global__ void prep_weights_kernel(const float* __restrict__ R,
                                    const float* __restrict__ Wih,
                                    const float* __restrict__ Whh) {
    int i = blockIdx.x * 256 + threadIdx.x;     // 0 .. 28671
    if (i < 4096) {
        int o = i >> 6, k = i & 63;
        g_rt[o * 64 + k] = R[k * 64 + o];
    } else if (i < 4096 + 12288) {
        int j = i - 4096;
        int o = j >> 6, k = j & 63;
        g_wihT[o * 64 + k] = Wih[k * 192 + o];
    } else {
        int j = i - 4096 - 12288;
        int o = j >> 6, k = j & 63;
        g_whhT[o * 64 + k] = Whh[k * 192 + o];
    }
}

// ---------------- ew = h1 @ W2 + b2 via tensor cores (bf16 in, fp32 acc, bf16 out) ----
__global__ __launch_bounds__(256) void ew_gemm_tc(const float* __restrict__ bias) {
    __shared__ __nv_bfloat16 As[128][72];
    __shared__ __nv_bfloat16 Bs[128][72];
    int bm = blockIdx.y * 128, bn = blockIdx.x * 128;
    int tid = threadIdx.x;

#pragma unroll
    for (int p = 0; p < 4; p++) {
        int idx = tid + p * 256;
        int row = idx >> 3, c8 = (idx & 7) * 8;
        *(uint4*)&As[row][c8] = *(const uint4*)&g_h1b[(size_t)(bm + row) * 64 + c8];
        *(uint4*)&Bs[row][c8] = *(const uint4*)&g_w2t[(size_t)(bn + row) * 64 + c8];
    }
    __syncthreads();

    int w = tid >> 5, lane = tid & 31;
    int wm = (w >> 2) * 64, wn = (w & 3) * 32;
    int g = lane >> 2, t4 = lane & 3;

    float c[4][4][4];
#pragma unroll
    for (int mi = 0; mi < 4; mi++)
#pragma unroll
        for (int ni = 0; ni < 4; ni++)
#pragma unroll
            for (int r = 0; r < 4; r++) c[mi][ni][r] = 0.f;

#pragma unroll
    for (int ks = 0; ks < 4; ks++) {
        int k0 = ks * 16;
        uint32_t a[4][4], b[4][2];
#pragma unroll
        for (int mi = 0; mi < 4; mi++) {
            int r0 = wm + mi * 16 + g;
            a[mi][0] = *(const uint32_t*)&As[r0][k0 + 2 * t4];
            a[mi][1] = *(const uint32_t*)&As[r0 + 8][k0 + 2 * t4];
            a[mi][2] = *(const uint32_t*)&As[r0][k0 + 2 * t4 + 8];
            a[mi][3] = *(const uint32_t*)&As[r0 + 8][k0 + 2 * t4 + 8];
        }
#pragma unroll
        for (int ni = 0; ni < 4; ni++) {
            int nr = wn + ni * 8 + g;
            b[ni][0] = *(const uint32_t*)&Bs[nr][k0 + 2 * t4];
            b[ni][1] = *(const uint32_t*)&Bs[nr][k0 + 2 * t4 + 8];
        }
#pragma unroll
        for (int mi = 0; mi < 4; mi++)
#pragma unroll
            for (int ni = 0; ni < 4; ni++)
                mma_bf16(c[mi][ni], a[mi], b[ni]);
    }

#pragma unroll
    for (int mi = 0; mi < 4; mi++) {
        int row0 = bm + wm + mi * 16 + g;
#pragma unroll
        for (int ni = 0; ni < 4; ni++) {
            int n = bn + wn + ni * 8 + 2 * t4;
            float b0 = bias[n], b1v = bias[n + 1];
            __nv_bfloat162 v0 = __floats2bfloat162_rn(c[mi][ni][0] + b0, c[mi][ni][1] + b1v);
            __nv_bfloat162 v1 = __floats2bfloat162_rn(c[mi][ni][2] + b0, c[mi][ni][3] + b1v);
            *reinterpret_cast<__nv_bfloat162*>(&g_ewb[(size_t)row0 * 4096 + n]) = v0;
            *reinterpret_cast<__nv_bfloat162*>(&g_ewb[(size_t)(row0 + 8) * 4096 + n]) = v1;
        }
    }
}

// ---------------- msg: agg[dst] += h[src] @ ew[e]   (bf16 weights, 8 edges/block) ----
__global__ __launch_bounds__(128) void msg_kernel(const int* __restrict__ src,
                                                  const int* __restrict__ dst) {
    __shared__ float hs[8][64];
    int tid = threadIdx.x;
    int slot = tid >> 4, t16 = tid & 15;
    int e = blockIdx.x * 8 + slot;
    int s = src[e];
    *(float4*)&hs[slot][t16 * 4] = *(const float4*)&g_h[(size_t)s * 64 + t16 * 4];
    __syncthreads();
    float4 acc = make_float4(0.f, 0.f, 0.f, 0.f);
    const uint2* ewp = reinterpret_cast<const uint2*>(g_ewb + (size_t)e * 4096 + t16 * 4);
#pragma unroll 8
    for (int i = 0; i < 64; i++) {
        float hv = hs[slot][i];
        uint2 raw = ewp[i * 16];
        float2 w01 = __bfloat1622float2(*reinterpret_cast<__nv_bfloat162*>(&raw.x));
        float2 w23 = __bfloat1622float2(*reinterpret_cast<__nv_bfloat162*>(&raw.y));
        acc.x += hv * w01.x; acc.y += hv * w01.y;
        acc.z += hv * w23.x; acc.w += hv * w23.y;
    }
    int d = dst[e];
    float* ap = &g_agg[(size_t)d * 64 + t16 * 4];
    atomicAdd(ap + 0, acc.x); atomicAdd(ap + 1, acc.y);
    atomicAdd(ap + 2, acc.z); atomicAdd(ap + 3, acc.w);
}

// ---------------- tf32 tensor-core NNConv epilogue + GRU (64 nodes/block, 8 warps) --
// warp w owns output dims [w*8, w*8+8) and ALL 3 gates for those dims.
__global__ __launch_bounds__(256) void node_update_tc(
    const float* __restrict__ cbias,
    const float* __restrict__ bih, const float* __restrict__ bhh) {
    __shared__ float hsm[64][68];
    __shared__ float msm[64][68];
    int n0 = blockIdx.x * 64;
    int tid = threadIdx.x;

    // load h tile -> fp32 smem
#pragma unroll
    for (int i = 0; i < 4; i++) {
        int idx = tid + i * 256;
        int row = idx >> 4, c4 = (idx & 15) * 4;
        *(float4*)&hsm[row][c4] = *(const float4*)&g_h[(size_t)(n0 + row) * 64 + c4];
    }
    __syncthreads();

    int w = tid >> 5, lane = tid & 31;
    int g = lane >> 2, t4 = lane & 3;
    int c0 = w * 8 + 2 * t4;

    // ---- phase B: h @ R^T for this warp's 8 columns (tf32, K=64 in 8 steps) ----
    float accB[4][4] = {};
#pragma unroll
    for (int ks = 0; ks < 8; ks++) {
        int k0 = ks * 8;
        uint32_t rb[2];
        int nrow = w * 8 + g;
        rb[0] = f2tf32(g_rt[nrow * 64 + k0 + t4]);
        rb[1] = f2tf32(g_rt[nrow * 64 + k0 + t4 + 4]);
#pragma unroll
        for (int mt = 0; mt < 4; mt++) {
            int r0 = mt * 16 + g;
            uint32_t a[4];
            a[0] = f2tf32(hsm[r0][k0 + t4]);
            a[1] = f2tf32(hsm[r0 + 8][k0 + t4]);
            a[2] = f2tf32(hsm[r0][k0 + t4 + 4]);
            a[3] = f2tf32(hsm[r0 + 8][k0 + t4 + 4]);
            mma_tf32(accB[mt], a, rb);
        }
    }
    // epilogue B: m = lrelu(agg*invdeg + h@R + cbias); zero agg for next iter
    {
        float2 cb = *(const float2*)&cbias[c0];
#pragma unroll
        for (int mt = 0; mt < 4; mt++) {
#pragma unroll
            for (int half = 0; half < 2; half++) {
                int row = mt * 16 + g + half * 8;
                int node = n0 + row;
                float inv = g_deg[node];
                float2 ag = *(float2*)&g_agg[(size_t)node * 64 + c0];
                *(float2*)&g_agg[(size_t)node * 64 + c0] = make_float2(0.f, 0.f);
                msm[row][c0]     = lrelu(ag.x * inv + accB[mt][half * 2 + 0] + cb.x);
                msm[row][c0 + 1] = lrelu(ag.y * inv + accB[mt][half * 2 + 1] + cb.y);
            }
        }
    }
    __syncthreads();

    // ---- phase C: gi = m @ Wih^T, gh = h @ Whh^T (3 gates x this warp's 8 cols) ----
    float accI[4][3][4] = {};
    float accH[4][3][4] = {};
#pragma unroll
    for (int ks = 0; ks < 8; ks++) {
        int k0 = ks * 8;
        uint32_t bi[3][2], bh[3][2];
#pragma unroll
        for (int j = 0; j < 3; j++) {
            int nrow = j * 64 + w * 8 + g;
            bi[j][0] = f2tf32(g_wihT[nrow * 64 + k0 + t4]);
            bi[j][1] = f2tf32(g_wihT[nrow * 64 + k0 + t4 + 4]);
            bh[j][0] = f2tf32(g_whhT[nrow * 64 + k0 + t4]);
            bh[j][1] = f2tf32(g_whhT[nrow * 64 + k0 + t4 + 4]);
        }
#pragma unroll
        for (int mt = 0; mt < 4; mt++) {
            int r0 = mt * 16 + g;
            uint32_t am[4], ah[4];
            am[0] = f2tf32(msm[r0][k0 + t4]);
            am[1] = f2tf32(msm[r0 + 8][k0 + t4]);
            am[2] = f2tf32(msm[r0][k0 + t4 + 4]);
            am[3] = f2tf32(msm[r0 + 8][k0 + t4 + 4]);
            ah[0] = f2tf32(hsm[r0][k0 + t4]);
            ah[1] = f2tf32(hsm[r0 + 8][k0 + t4]);
            ah[2] = f2tf32(hsm[r0][k0 + t4 + 4]);
            ah[3] = f2tf32(hsm[r0 + 8][k0 + t4 + 4]);
#pragma unroll
            for (int j = 0; j < 3; j++) {
                mma_tf32(accI[mt][j], am, bi[j]);
                mma_tf32(accH[mt][j], ah, bh[j]);
            }
        }
    }

    // epilogue C: GRU pointwise, fp32 blend with old h
    float2 b_ir = *(const float2*)&bih[c0];
    float2 b_iz = *(const float2*)&bih[64 + c0];
    float2 b_in = *(const float2*)&bih[128 + c0];
    float2 b_hr = *(const float2*)&bhh[c0];
    float2 b_hz = *(const float2*)&bhh[64 + c0];
    float2 b_hn = *(const float2*)&bhh[128 + c0];
#pragma unroll
    for (int mt = 0; mt < 4; mt++) {
#pragma unroll
        for (int half = 0; half < 2; half++) {
            int row = mt * 16 + g + half * 8;
            int node = n0 + row;
            int o = half * 2;
            float2 hold = make_float2(hsm[row][c0], hsm[row][c0 + 1]);
            float rx = sigm(accI[mt][0][o] + b_ir.x + accH[mt][0][o] + b_hr.x);
            float zx = sigm(accI[mt][1][o] + b_iz.x + accH[mt][1][o] + b_hz.x);
            float nx = tanhf(accI[mt][2][o] + b_in.x + rx * (accH[mt][2][o] + b_hn.x));
            float ry = sigm(accI[mt][0][o + 1] + b_ir.y + accH[mt][0][o + 1] + b_hr.y);
            float zy = sigm(accI[mt][1][o + 1] + b_iz.y + accH[mt][1][o + 1] + b_hz.y);
            float ny = tanhf(accI[mt][2][o + 1] + b_in.y + ry * (accH[mt][2][o + 1] + b_hn.y));
            float2 hn;
            hn.x = (1.f - zx) * nx + zx * hold.x;
            hn.y = (1.f - zy) * ny + zy * hold.y;
            *(float2*)&g_h[(size_t)node * 64 + c0] = hn;
        }
    }
}

// ---------------- stem head ----------------
__global__ __launch_bounds__(128) void stem_kernel(const int* __restrict__ idx,
                                                   const float* __restrict__ W1, const float* __restrict__ b1,
                                                   const float* __restrict__ W2, const float* __restrict__ b2,
                                                   float* __restrict__ outp) {
    __shared__ float row[64], hid[64];
    int s = blockIdx.x, t = threadIdx.x;
    int atom = idx[s];
    if (t < 64) row[t] = g_h[(size_t)atom * 64 + t];
    __syncthreads();
    if (t < 64) {
        float acc = b1[t];
#pragma unroll
        for (int i = 0; i < 64; i++) acc += row[i] * W1[i * 64 + t];
        hid[t] = lrelu(acc);
    }
    __syncthreads();
    for (int o = t; o < NUM_OUT; o += 128) {
        float acc = b2[o];
#pragma unroll
        for (int i = 0; i < 64; i++) acc += hid[i] * W2[i * NUM_OUT + o];
        outp[512 + (size_t)s * NUM_OUT + o] = acc;
    }
}

// ---------------- jbond head ----------------
__global__ __launch_bounds__(128) void jbond_kernel(const int* __restrict__ idx,
                                                    const float* __restrict__ W1, const float* __restrict__ b1,
                                                    const float* __restrict__ w2, const float* __restrict__ b2,
                                                    float* __restrict__ outp) {
    __shared__ float row[2][64];
    __shared__ float warpsum[4];
    int jb = blockIdx.x, t = threadIdx.x;
    int a = t >> 6, tt = t & 63;
    int atom = idx[jb * 2 + a];
    row[a][tt] = g_h[(size_t)atom * 64 + tt];
    __syncthreads();
    float acc = b1[tt];
#pragma unroll
    for (int i = 0; i < 64; i++) acc += row[a][i] * W1[i * 64 + tt];
    float p = lrelu(acc) * w2[tt];
#pragma unroll
    for (int off = 16; off; off >>= 1) p += __shfl_xor_sync(0xffffffffu, p, off);
    if ((t & 31) == 0) warpsum[t >> 5] = p;
    __syncthreads();
    if (t == 0) {
        float p0 = warpsum[0] + warpsum[1] + b2[0];
        float p1 = warpsum[2] + warpsum[3] + b2[0];
        outp[512 + (size_t)N_STEMS * NUM_OUT + jb] = 0.5f * (p0 + p1);
    }
}

// ---------------- Set2Set q (bias-only; identical for all graphs) ----------------
__global__ void s2s_q_kernel(const float* __restrict__ bih, const float* __restrict__ bhh) {
    int d = threadIdx.x;
    float bi = bih[d]       + bhh[d];
    float bg = bih[128 + d] + bhh[128 + d];
    float bo = bih[192 + d] + bhh[192 + d];
    float c = sigm(bi) * tanhf(bg);
    g_q[d] = sigm(bo) * tanhf(c);
}

// ---------------- per-graph attention pool + lin_out ----------------
__global__ __launch_bounds__(128) void pool_kernel(const int* __restrict__ batch,
                                                   const float* __restrict__ W, const float* __restrict__ bias,
                                                   float* __restrict__ outp) {
    __shared__ int s_lo, s_hi;
    __shared__ float s_max[4], s_ws[4], s_pool[4][64], s_r[64];
    int b = blockIdx.x, t = threadIdx.x;
    if (t == 0) {
        int lo = 0, hi = N_NODES;
        while (lo < hi) { int m = (lo + hi) >> 1; if (batch[m] < b) lo = m + 1; else hi = m; }
        s_lo = lo;
        int lo2 = lo, hi2 = N_NODES;
        while (lo2 < hi2) { int m = (lo2 + hi2) >> 1; if (batch[m] < b + 1) lo2 = m + 1; else hi2 = m; }
        s_hi = lo2;
    }
    __syncthreads();
    int lo = s_lo, hi = s_hi;
    int warp = t >> 5, lane = t & 31;
    float q0 = g_q[lane], q1 = g_q[32 + lane];
    float lmax = -3.4e38f;
    for (int n = lo + warp; n < hi; n += 4) {
        float v = g_h[(size_t)n * 64 + lane] * q0 + g_h[(size_t)n * 64 + 32 + lane] * q1;
#pragma unroll
        for (int off = 16; off; off >>= 1) v += __shfl_xor_sync(0xffffffffu, v, off);
        lmax = fmaxf(lmax, v);
    }
    if (lane == 0) s_max[warp] = lmax;
    __syncthreads();
    float emax = fmaxf(fmaxf(s_max[0], s_max[1]), fmaxf(s_max[2], s_max[3]));
    float p0 = 0.f, p1 = 0.f, ws = 0.f;
    for (int n = lo + warp; n < hi; n += 4) {
        float h0 = g_h[(size_t)n * 64 + lane], h1v = g_h[(size_t)n * 64 + 32 + lane];
        float v = h0 * q0 + h1v * q1;
#pragma unroll
        for (int off = 16; off; off >>= 1) v += __shfl_xor_sync(0xffffffffu, v, off);
        float c = expf(v - emax);
        p0 += c * h0; p1 += c * h1v; ws += c;
    }
    s_pool[warp][lane] = p0; s_pool[warp][32 + lane] = p1;
    if (lane == 0) s_ws[warp] = ws;
    __syncthreads();
    if (t < 64) {
        float ps = s_pool[0][t] + s_pool[1][t] + s_pool[2][t] + s_pool[3][t];
        float wtot = s_ws[0] + s_ws[1] + s_ws[2] + s_ws[3];
        s_r[t] = (wtot > 0.f) ? ps / wtot : 0.f;
    }
    __syncthreads();
    if (t < 2) {
        float acc = bias[t];
        for (int d = 0; d < 64; d++)
            acc += g_q[d] * W[d * 2 + t] + s_r[d] * W[(64 + d) * 2 + t];
        outp[b * 2 + t] = acc;
    }
}

// ---------------- launch ----------------
extern "C" void kernel_launch(void* const* d_in, const int* in_sizes, int n_in,
                              void* d_out, int out_size) {
    const float* x          = (const float*)d_in[0];
    const float* edge_attr  = (const float*)d_in[1];
    const int*   edge_index = (const int*)  d_in[2];
    const int*   batch      = (const int*)  d_in[3];
    const int*   stem_idx   = (const int*)  d_in[4];
    const int*   jbond_idx  = (const int*)  d_in[5];
    const float* lin0_w   = (const float*)d_in[6];
    const float* lin0_b   = (const float*)d_in[7];
    const float* net_w1   = (const float*)d_in[8];
    const float* net_b1   = (const float*)d_in[9];
    const float* net_w2   = (const float*)d_in[10];
    const float* net_b2   = (const float*)d_in[11];
    const float* conv_root= (const float*)d_in[12];
    const float* conv_bias= (const float*)d_in[13];
    const float* gru_w_ih = (const float*)d_in[14];
    const float* gru_w_hh = (const float*)d_in[15];
    const float* gru_b_ih = (const float*)d_in[16];
    const float* gru_b_hh = (const float*)d_in[17];
    const float* n2s_w1   = (const float*)d_in[18];
    const float* n2s_b1   = (const float*)d_in[19];
    const float* n2s_w2   = (const float*)d_in[20];
    const float* n2s_b2   = (const float*)d_in[21];
    const float* n2j_w1   = (const float*)d_in[22];
    const float* n2j_b1   = (const float*)d_in[23];
    const float* n2j_w2   = (const float*)d_in[24];
    const float* n2j_b2   = (const float*)d_in[25];
    const float* s2s_b_ih = (const float*)d_in[28];
    const float* s2s_b_hh = (const float*)d_in[29];
    const float* lin_out_w= (const float*)d_in[30];
    const float* lin_out_b= (const float*)d_in[31];
    float* out = (float*)d_out;

    const int* src = edge_index;             // edge_index[0]
    const int* dst = edge_index + N_EDGES;   // edge_index[1]

    zero_deg_kernel<<<N_NODES / 256, 256>>>();
    deg_kernel<<<(N_EDGES + 255) / 256, 256>>>(dst);
    invdeg_kernel<<<N_NODES / 256, 256>>>();
    zero_agg_kernel<<<N_NODES * DIM / 4 / 256, 256>>>();
    lin0_kernel<<<N_NODES * DIM / 256, 256>>>(x, lin0_w, lin0_b);
    h1_kernel<<<N_EDGES * DIM / 256, 256>>>(edge_attr, net_w1, net_b1);
    w2t_kernel<<<DIM * 4096 / 256, 256>>>(net_w2);
    prep_weights_kernel<<<112, 256>>>(conv_root, gru_w_ih, gru_w_hh);
    ew_gemm_tc<<<dim3(4096 / 128, N_EDGES / 128), 256>>>(net_b2);

    for (int it = 0; it < 6; it++) {
        msg_kernel<<<N_EDGES / 8, 128>>>(src, dst);
        node_update_tc<<<N_NODES / 64, 256>>>(conv_bias, gru_b_ih, gru_b_hh);
    }

    stem_kernel<<<N_STEMS, 128>>>(stem_idx, n2s_w1, n2s_b1, n2s_w2, n2s_b2, out);
    jbond_kernel<<<N_JBONDS, 128>>>(jbond_idx, n2j_w1, n2j_b1, n2j_w2, n2j_b2, out);
    s2s_q_kernel<<<1, 64>>>(s2s_b_ih, s2s_b_hh);
    pool_kernel<<<N_GRAPHS, 128>>>(batch, lin_out_w, lin_out_b, out);
}

// round 6
// speedup vs baseline: 2.2763x; 1.1199x over previous
#include <cuda_runtime.h>
#include <cuda_bf16.h>
#include <cstdint>
#include <math.h>

#define N_NODES   8192
#define N_EDGES   16384
#define N_GRAPHS  256
#define N_STEMS   2048
#define N_JBONDS  1024
#define DIM       64
#define NUM_FEAT  14
#define NUM_OUT   105

// ---------------- scratch (device globals; no allocations allowed) ----------------
__device__ __nv_bfloat16 g_w2r[65 * 64 * 64];   // W2 rearranged [chunk k][o][i] bf16; chunk 64 = B2
__device__ float g_h1f[N_EDGES * DIM];          // edge-net hidden (fp32)
__device__ float g_rt[64 * 64];                 // conv_root^T [o][i] fp32
__device__ float g_wihT[192 * 64];              // gru_w_ih^T [o][i] fp32
__device__ float g_whhT[192 * 64];              // gru_w_hh^T [o][i] fp32
__device__ float g_h[N_NODES * DIM];            // node state
__device__ float g_agg[N_NODES * DIM];          // scatter accumulator
__device__ float g_deg[N_NODES];                // becomes 1/max(deg,1)
__device__ float g_q[DIM];

__device__ __forceinline__ float lrelu(float v) { return v > 0.f ? v : 0.01f * v; }
__device__ __forceinline__ float sigm(float v)  { return 1.f / (1.f + expf(-v)); }

__device__ __forceinline__ void mma_bf16(float* c, const uint32_t* a, const uint32_t* b) {
    asm volatile(
        "mma.sync.aligned.m16n8k16.row.col.f32.bf16.bf16.f32 "
        "{%0,%1,%2,%3}, {%4,%5,%6,%7}, {%8,%9}, {%0,%1,%2,%3};"
        : "+f"(c[0]), "+f"(c[1]), "+f"(c[2]), "+f"(c[3])
        : "r"(a[0]), "r"(a[1]), "r"(a[2]), "r"(a[3]), "r"(b[0]), "r"(b[1]));
}

__device__ __forceinline__ uint32_t f2tf32(float f) {
    uint32_t r;
    asm("cvt.rna.tf32.f32 %0, %1;" : "=r"(r) : "f"(f));
    return r;
}

__device__ __forceinline__ void mma_tf32(float* c, const uint32_t* a, const uint32_t* b) {
    asm volatile(
        "mma.sync.aligned.m16n8k8.row.col.f32.tf32.tf32.f32 "
        "{%0,%1,%2,%3}, {%4,%5,%6,%7}, {%8,%9}, {%0,%1,%2,%3};"
        : "+f"(c[0]), "+f"(c[1]), "+f"(c[2]), "+f"(c[3])
        : "r"(a[0]), "r"(a[1]), "r"(a[2]), "r"(a[3]), "r"(b[0]), "r"(b[1]));
}

// ---------------- degree / init ----------------
__global__ void zero_deg_kernel() {
    g_deg[blockIdx.x * 256 + threadIdx.x] = 0.f;
}
__global__ void deg_kernel(const int* __restrict__ dst) {
    int e = blockIdx.x * 256 + threadIdx.x;
    if (e < N_EDGES) atomicAdd(&g_deg[dst[e]], 1.0f);
}
__global__ void invdeg_kernel() {
    int i = blockIdx.x * 256 + threadIdx.x;
    g_deg[i] = 1.0f / fmaxf(g_deg[i], 1.0f);
}
__global__ void zero_agg_kernel() {
    int i = blockIdx.x * 256 + threadIdx.x;
    ((float4*)g_agg)[i] = make_float4(0.f, 0.f, 0.f, 0.f);
}

// ---------------- lin0: h = lrelu(x @ W + b) ----------------
__global__ void lin0_kernel(const float* __restrict__ x,
                            const float* __restrict__ W,
                            const float* __restrict__ b) {
    int tid = blockIdx.x * 256 + threadIdx.x;
    int n = tid >> 6, o = tid & 63;
    float acc = b[o];
#pragma unroll
    for (int i = 0; i < NUM_FEAT; i++) acc += x[n * NUM_FEAT + i] * W[i * DIM + o];
    g_h[(size_t)n * DIM + o] = lrelu(acc);
}

// ---------------- edge net hidden: h1 = lrelu(ea @ W1 + b1), fp32 ----------------
__global__ void h1_kernel(const float* __restrict__ ea,
                          const float* __restrict__ W1,
                          const float* __restrict__ b1) {
    int tid = blockIdx.x * 256 + threadIdx.x;
    int e = tid >> 6, k = tid & 63;
    float acc = b1[k];
#pragma unroll
    for (int i = 0; i < 4; i++) acc += ea[e * 4 + i] * W1[i * DIM + k];
    g_h1f[(size_t)e * DIM + k] = lrelu(acc);
}

// ---------------- W2 rearrange: g_w2r[k][o][i] = W2[k][i*64+o]; chunk 64 = B2 ------
__global__ void w2r_kernel(const float* __restrict__ W2, const float* __restrict__ b2) {
    int idx = blockIdx.x * 256 + threadIdx.x;
    if (idx >= 65 * 4096) return;
    int c = idx >> 12, r = idx & 4095;
    int o = r >> 6, i = r & 63;
    float v = (c < 64) ? W2[(c << 12) + (i << 6) + o] : b2[(i << 6) + o];
    g_w2r[idx] = __float2bfloat16(v);
}

// ---------------- GRU/root weights -> transposed fp32 ----------------
__global__ void prep_weights_kernel(const float* __restrict__ R,
                                    const float* __restrict__ Wih,
                                    const float* __restrict__ Whh) {
    int i = blockIdx.x * 256 + threadIdx.x;     // 0 .. 28671
    if (i < 4096) {
        int o = i >> 6, k = i & 63;
        g_rt[o * 64 + k] = R[k * 64 + o];
    } else if (i < 4096 + 12288) {
        int j = i - 4096;
        int o = j >> 6, k = j & 63;
        g_wihT[o * 64 + k] = Wih[k * 192 + o];
    } else {
        int j = i - 4096 - 12288;
        int o = j >> 6, k = j & 63;
        g_whhT[o * 64 + k] = Whh[k * 192 + o];
    }
}

// ================= fused factorized message GEMM ==================================
// msg_e = sum_k h1_ek * (v_e @ W2_k) + v_e @ B2,  v_e = h[src(e)], scatter to agg[dst].
// Block: 128 edges, 256 threads (warps 4m x 2n). W2 streamed via cp.async (2-stage).
//
// dynamic smem layout (bytes):
//   [0, 73728)        w2sm: 2 bufs x [4 chunks][64 o][72 i] bf16
//   [73728, 92160)    vsm:  [128][72] bf16
//   [92160, 126976)   h1sm: [128][68] fp32
//   [126976, 127488)  dssm: [128] int
#define MSG_SMEM_W2   0
#define MSG_SMEM_V    73728
#define MSG_SMEM_H1   92160
#define MSG_SMEM_DS   126976
#define MSG_SMEM_TOTAL 127488
#define W2BUF_BYTES   36864

__device__ __forceinline__ void prefetch_w2(int base_chunk, int nch, int buf,
                                            int tid, uint32_t smem_base) {
    int tasks = nch * 512;                      // nch * 64 rows * 8 segs
    for (int idx = tid; idx < tasks; idx += 256) {
        int cc = idx >> 9;
        int o  = (idx >> 3) & 63;
        int s  = idx & 7;
        const __nv_bfloat16* gp = &g_w2r[((size_t)(base_chunk + cc) * 64 + o) * 64 + s * 8];
        uint32_t sp = smem_base + MSG_SMEM_W2 + buf * W2BUF_BYTES
                      + ((cc * 64 + o) * 72 + s * 8) * 2;
        asm volatile("cp.async.cg.shared.global [%0], [%1], 16;" :: "r"(sp), "l"(gp));
    }
    asm volatile("cp.async.commit_group;" ::: "memory");
}

__global__ __launch_bounds__(256, 1) void msg_gemm(const int* __restrict__ src,
                                                   const int* __restrict__ dst) {
    extern __shared__ char smem[];
    __nv_bfloat16* vsm = (__nv_bfloat16*)(smem + MSG_SMEM_V);
    float* h1sm = (float*)(smem + MSG_SMEM_H1);
    int* dssm = (int*)(smem + MSG_SMEM_DS);
    uint32_t smem_base = (uint32_t)__cvta_generic_to_shared(smem);

    int tid = threadIdx.x;
    int e0 = blockIdx.x * 128;

    // kick off W2 group 0 (chunks 0..3) into buf 0
    prefetch_w2(0, 4, 0, tid, smem_base);

    // gather v (bf16), h1 (fp32), dst
    if (tid < 128) dssm[tid] = dst[e0 + tid];
#pragma unroll
    for (int p = 0; p < 8; p++) {
        int idx = tid + p * 256;                // 2048 tasks
        int row = idx >> 4, seg = idx & 15;
        int s = src[e0 + row];
        float4 v = *(const float4*)&g_h[(size_t)s * 64 + seg * 4];
        __nv_bfloat162 p0 = __floats2bfloat162_rn(v.x, v.y);
        __nv_bfloat162 p1 = __floats2bfloat162_rn(v.z, v.w);
        uint2 u;
        u.x = *(uint32_t*)&p0; u.y = *(uint32_t*)&p1;
        *(uint2*)&vsm[row * 72 + seg * 4] = u;
        float4 hv = *(const float4*)&g_h1f[(size_t)(e0 + row) * 64 + seg * 4];
        *(float4*)&h1sm[row * 68 + seg * 4] = hv;
    }
    __syncthreads();

    int w = tid >> 5, lane = tid & 31;
    int warpM = w >> 1, warpN = w & 1;
    int rowbase = warpM * 32;
    int g = lane >> 2, t4 = lane & 3;

    // v fragments (persist in registers for all 65 chunks)
    uint32_t vfrag[2][4][4];
#pragma unroll
    for (int mt = 0; mt < 2; mt++)
#pragma unroll
        for (int ks = 0; ks < 4; ks++) {
            int r0 = rowbase + mt * 16 + g;
            int cl = ks * 16 + 2 * t4;
            vfrag[mt][ks][0] = *(const uint32_t*)&vsm[r0 * 72 + cl];
            vfrag[mt][ks][1] = *(const uint32_t*)&vsm[(r0 + 8) * 72 + cl];
            vfrag[mt][ks][2] = *(const uint32_t*)&vsm[r0 * 72 + cl + 8];
            vfrag[mt][ks][3] = *(const uint32_t*)&vsm[(r0 + 8) * 72 + cl + 8];
        }

    float c[2][4][4];
#pragma unroll
    for (int mt = 0; mt < 2; mt++)
#pragma unroll
        for (int ni = 0; ni < 4; ni++)
#pragma unroll
            for (int r = 0; r < 4; r++) c[mt][ni][r] = 0.f;

#pragma unroll 1
    for (int grp = 0; grp < 16; grp++) {
        asm volatile("cp.async.wait_group 0;" ::: "memory");
        __syncthreads();
        int buf = grp & 1;
        if (grp < 15) prefetch_w2((grp + 1) * 4, 4, (grp + 1) & 1, tid, smem_base);
        else          prefetch_w2(64, 1, 0, tid, smem_base);
        const __nv_bfloat16* w2p =
            (const __nv_bfloat16*)(smem + MSG_SMEM_W2 + buf * W2BUF_BYTES);
#pragma unroll 1
        for (int cc = 0; cc < 4; cc++) {
            int k = grp * 4 + cc;
            float tc[2][4][4];
#pragma unroll
            for (int mt = 0; mt < 2; mt++)
#pragma unroll
                for (int ni = 0; ni < 4; ni++)
#pragma unroll
                    for (int r = 0; r < 4; r++) tc[mt][ni][r] = 0.f;
#pragma unroll
            for (int ks = 0; ks < 4; ks++) {
                uint32_t b[4][2];
#pragma unroll
                for (int ni = 0; ni < 4; ni++) {
                    int orow = warpN * 32 + ni * 8 + g;
                    int ib = ks * 16 + 2 * t4;
                    b[ni][0] = *(const uint32_t*)&w2p[(cc * 64 + orow) * 72 + ib];
                    b[ni][1] = *(const uint32_t*)&w2p[(cc * 64 + orow) * 72 + ib + 8];
                }
#pragma unroll
                for (int mt = 0; mt < 2; mt++)
#pragma unroll
                    for (int ni = 0; ni < 4; ni++)
                        mma_bf16(tc[mt][ni], vfrag[mt][ks], b[ni]);
            }
            // fp32 h1 scaling on the accumulator side
#pragma unroll
            for (int mt = 0; mt < 2; mt++) {
                float hA = h1sm[(rowbase + mt * 16 + g) * 68 + k];
                float hB = h1sm[(rowbase + mt * 16 + g + 8) * 68 + k];
#pragma unroll
                for (int ni = 0; ni < 4; ni++) {
                    c[mt][ni][0] += hA * tc[mt][ni][0];
                    c[mt][ni][1] += hA * tc[mt][ni][1];
                    c[mt][ni][2] += hB * tc[mt][ni][2];
                    c[mt][ni][3] += hB * tc[mt][ni][3];
                }
            }
        }
        __syncthreads();
    }

    // B2 chunk (unit coefficient) — accumulate directly into c
    asm volatile("cp.async.wait_group 0;" ::: "memory");
    __syncthreads();
    {
        const __nv_bfloat16* w2p = (const __nv_bfloat16*)(smem + MSG_SMEM_W2);  // buf 0
#pragma unroll
        for (int ks = 0; ks < 4; ks++) {
            uint32_t b[4][2];
#pragma unroll
            for (int ni = 0; ni < 4; ni++) {
                int orow = warpN * 32 + ni * 8 + g;
                int ib = ks * 16 + 2 * t4;
                b[ni][0] = *(const uint32_t*)&w2p[orow * 72 + ib];
                b[ni][1] = *(const uint32_t*)&w2p[orow * 72 + ib + 8];
            }
#pragma unroll
            for (int mt = 0; mt < 2; mt++)
#pragma unroll
                for (int ni = 0; ni < 4; ni++)
                    mma_bf16(c[mt][ni], vfrag[mt][ks], b[ni]);
        }
    }

    // scatter into agg
#pragma unroll
    for (int mt = 0; mt < 2; mt++)
#pragma unroll
        for (int half = 0; half < 2; half++) {
            int row = rowbase + mt * 16 + g + half * 8;
            int d = dssm[row];
            float* ap = &g_agg[(size_t)d * 64 + warpN * 32];
#pragma unroll
            for (int ni = 0; ni < 4; ni++) {
                atomicAdd(&ap[ni * 8 + 2 * t4],     c[mt][ni][half * 2 + 0]);
                atomicAdd(&ap[ni * 8 + 2 * t4 + 1], c[mt][ni][half * 2 + 1]);
            }
        }
}

// ---------------- tf32 tensor-core NNConv epilogue + GRU (64 nodes/block) ----------
__global__ __launch_bounds__(256) void node_update_tc(
    const float* __restrict__ cbias,
    const float* __restrict__ bih, const float* __restrict__ bhh) {
    __shared__ float hsm[64][68];
    __shared__ float msm[64][68];
    int n0 = blockIdx.x * 64;
    int tid = threadIdx.x;

#pragma unroll
    for (int i = 0; i < 4; i++) {
        int idx = tid + i * 256;
        int row = idx >> 4, c4 = (idx & 15) * 4;
        *(float4*)&hsm[row][c4] = *(const float4*)&g_h[(size_t)(n0 + row) * 64 + c4];
    }
    __syncthreads();

    int w = tid >> 5, lane = tid & 31;
    int g = lane >> 2, t4 = lane & 3;
    int c0 = w * 8 + 2 * t4;

    float accB[4][4] = {};
#pragma unroll
    for (int ks = 0; ks < 8; ks++) {
        int k0 = ks * 8;
        uint32_t rb[2];
        int nrow = w * 8 + g;
        rb[0] = f2tf32(g_rt[nrow * 64 + k0 + t4]);
        rb[1] = f2tf32(g_rt[nrow * 64 + k0 + t4 + 4]);
#pragma unroll
        for (int mt = 0; mt < 4; mt++) {
            int r0 = mt * 16 + g;
            uint32_t a[4];
            a[0] = f2tf32(hsm[r0][k0 + t4]);
            a[1] = f2tf32(hsm[r0 + 8][k0 + t4]);
            a[2] = f2tf32(hsm[r0][k0 + t4 + 4]);
            a[3] = f2tf32(hsm[r0 + 8][k0 + t4 + 4]);
            mma_tf32(accB[mt], a, rb);
        }
    }
    {
        float2 cb = *(const float2*)&cbias[c0];
#pragma unroll
        for (int mt = 0; mt < 4; mt++) {
#pragma unroll
            for (int half = 0; half < 2; half++) {
                int row = mt * 16 + g + half * 8;
                int node = n0 + row;
                float inv = g_deg[node];
                float2 ag = *(float2*)&g_agg[(size_t)node * 64 + c0];
                *(float2*)&g_agg[(size_t)node * 64 + c0] = make_float2(0.f, 0.f);
                msm[row][c0]     = lrelu(ag.x * inv + accB[mt][half * 2 + 0] + cb.x);
                msm[row][c0 + 1] = lrelu(ag.y * inv + accB[mt][half * 2 + 1] + cb.y);
            }
        }
    }
    __syncthreads();

    float accI[4][3][4] = {};
    float accH[4][3][4] = {};
#pragma unroll
    for (int ks = 0; ks < 8; ks++) {
        int k0 = ks * 8;
        uint32_t bi[3][2], bh[3][2];
#pragma unroll
        for (int j = 0; j < 3; j++) {
            int nrow = j * 64 + w * 8 + g;
            bi[j][0] = f2tf32(g_wihT[nrow * 64 + k0 + t4]);
            bi[j][1] = f2tf32(g_wihT[nrow * 64 + k0 + t4 + 4]);
            bh[j][0] = f2tf32(g_whhT[nrow * 64 + k0 + t4]);
            bh[j][1] = f2tf32(g_whhT[nrow * 64 + k0 + t4 + 4]);
        }
#pragma unroll
        for (int mt = 0; mt < 4; mt++) {
            int r0 = mt * 16 + g;
            uint32_t am[4], ah[4];
            am[0] = f2tf32(msm[r0][k0 + t4]);
            am[1] = f2tf32(msm[r0 + 8][k0 + t4]);
            am[2] = f2tf32(msm[r0][k0 + t4 + 4]);
            am[3] = f2tf32(msm[r0 + 8][k0 + t4 + 4]);
            ah[0] = f2tf32(hsm[r0][k0 + t4]);
            ah[1] = f2tf32(hsm[r0 + 8][k0 + t4]);
            ah[2] = f2tf32(hsm[r0][k0 + t4 + 4]);
            ah[3] = f2tf32(hsm[r0 + 8][k0 + t4 + 4]);
#pragma unroll
            for (int j = 0; j < 3; j++) {
                mma_tf32(accI[mt][j], am, bi[j]);
                mma_tf32(accH[mt][j], ah, bh[j]);
            }
        }
    }

    float2 b_ir = *(const float2*)&bih[c0];
    float2 b_iz = *(const float2*)&bih[64 + c0];
    float2 b_in = *(const float2*)&bih[128 + c0];
    float2 b_hr = *(const float2*)&bhh[c0];
    float2 b_hz = *(const float2*)&bhh[64 + c0];
    float2 b_hn = *(const float2*)&bhh[128 + c0];
#pragma unroll
    for (int mt = 0; mt < 4; mt++) {
#pragma unroll
        for (int half = 0; half < 2; half++) {
            int row = mt * 16 + g + half * 8;
            int node = n0 + row;
            int o = half * 2;
            float2 hold = make_float2(hsm[row][c0], hsm[row][c0 + 1]);
            float rx = sigm(accI[mt][0][o] + b_ir.x + accH[mt][0][o] + b_hr.x);
            float zx = sigm(accI[mt][1][o] + b_iz.x + accH[mt][1][o] + b_hz.x);
            float nx = tanhf(accI[mt][2][o] + b_in.x + rx * (accH[mt][2][o] + b_hn.x));
            float ry = sigm(accI[mt][0][o + 1] + b_ir.y + accH[mt][0][o + 1] + b_hr.y);
            float zy = sigm(accI[mt][1][o + 1] + b_iz.y + accH[mt][1][o + 1] + b_hz.y);
            float ny = tanhf(accI[mt][2][o + 1] + b_in.y + ry * (accH[mt][2][o + 1] + b_hn.y));
            float2 hn;
            hn.x = (1.f - zx) * nx + zx * hold.x;
            hn.y = (1.f - zy) * ny + zy * hold.y;
            *(float2*)&g_h[(size_t)node * 64 + c0] = hn;
        }
    }
}

// ---------------- stem head ----------------
__global__ __launch_bounds__(128) void stem_kernel(const int* __restrict__ idx,
                                                   const float* __restrict__ W1, const float* __restrict__ b1,
                                                   const float* __restrict__ W2, const float* __restrict__ b2,
                                                   float* __restrict__ outp) {
    __shared__ float row[64], hid[64];
    int s = blockIdx.x, t = threadIdx.x;
    int atom = idx[s];
    if (t < 64) row[t] = g_h[(size_t)atom * 64 + t];
    __syncthreads();
    if (t < 64) {
        float acc = b1[t];
#pragma unroll
        for (int i = 0; i < 64; i++) acc += row[i] * W1[i * 64 + t];
        hid[t] = lrelu(acc);
    }
    __syncthreads();
    for (int o = t; o < NUM_OUT; o += 128) {
        float acc = b2[o];
#pragma unroll
        for (int i = 0; i < 64; i++) acc += hid[i] * W2[i * NUM_OUT + o];
        outp[512 + (size_t)s * NUM_OUT + o] = acc;
    }
}

// ---------------- jbond head ----------------
__global__ __launch_bounds__(128) void jbond_kernel(const int* __restrict__ idx,
                                                    const float* __restrict__ W1, const float* __restrict__ b1,
                                                    const float* __restrict__ w2, const float* __restrict__ b2,
                                                    float* __restrict__ outp) {
    __shared__ float row[2][64];
    __shared__ float warpsum[4];
    int jb = blockIdx.x, t = threadIdx.x;
    int a = t >> 6, tt = t & 63;
    int atom = idx[jb * 2 + a];
    row[a][tt] = g_h[(size_t)atom * 64 + tt];
    __syncthreads();
    float acc = b1[tt];
#pragma unroll
    for (int i = 0; i < 64; i++) acc += row[a][i] * W1[i * 64 + tt];
    float p = lrelu(acc) * w2[tt];
#pragma unroll
    for (int off = 16; off; off >>= 1) p += __shfl_xor_sync(0xffffffffu, p, off);
    if ((t & 31) == 0) warpsum[t >> 5] = p;
    __syncthreads();
    if (t == 0) {
        float p0 = warpsum[0] + warpsum[1] + b2[0];
        float p1 = warpsum[2] + warpsum[3] + b2[0];
        outp[512 + (size_t)N_STEMS * NUM_OUT + jb] = 0.5f * (p0 + p1);
    }
}

// ---------------- Set2Set q (bias-only; identical for all graphs) ----------------
__global__ void s2s_q_kernel(const float* __restrict__ bih, const float* __restrict__ bhh) {
    int d = threadIdx.x;
    float bi = bih[d]       + bhh[d];
    float bg = bih[128 + d] + bhh[128 + d];
    float bo = bih[192 + d] + bhh[192 + d];
    float c = sigm(bi) * tanhf(bg);
    g_q[d] = sigm(bo) * tanhf(c);
}

// ---------------- per-graph attention pool + lin_out ----------------
__global__ __launch_bounds__(128) void pool_kernel(const int* __restrict__ batch,
                                                   const float* __restrict__ W, const float* __restrict__ bias,
                                                   float* __restrict__ outp) {
    __shared__ int s_lo, s_hi;
    __shared__ float s_max[4], s_ws[4], s_pool[4][64], s_r[64];
    int b = blockIdx.x, t = threadIdx.x;
    if (t == 0) {
        int lo = 0, hi = N_NODES;
        while (lo < hi) { int m = (lo + hi) >> 1; if (batch[m] < b) lo = m + 1; else hi = m; }
        s_lo = lo;
        int lo2 = lo, hi2 = N_NODES;
        while (lo2 < hi2) { int m = (lo2 + hi2) >> 1; if (batch[m] < b + 1) lo2 = m + 1; else hi2 = m; }
        s_hi = lo2;
    }
    __syncthreads();
    int lo = s_lo, hi = s_hi;
    int warp = t >> 5, lane = t & 31;
    float q0 = g_q[lane], q1 = g_q[32 + lane];
    float lmax = -3.4e38f;
    for (int n = lo + warp; n < hi; n += 4) {
        float v = g_h[(size_t)n * 64 + lane] * q0 + g_h[(size_t)n * 64 + 32 + lane] * q1;
#pragma unroll
        for (int off = 16; off; off >>= 1) v += __shfl_xor_sync(0xffffffffu, v, off);
        lmax = fmaxf(lmax, v);
    }
    if (lane == 0) s_max[warp] = lmax;
    __syncthreads();
    float emax = fmaxf(fmaxf(s_max[0], s_max[1]), fmaxf(s_max[2], s_max[3]));
    float p0 = 0.f, p1 = 0.f, ws = 0.f;
    for (int n = lo + warp; n < hi; n += 4) {
        float h0 = g_h[(size_t)n * 64 + lane], h1v = g_h[(size_t)n * 64 + 32 + lane];
        float v = h0 * q0 + h1v * q1;
#pragma unroll
        for (int off = 16; off; off >>= 1) v += __shfl_xor_sync(0xffffffffu, v, off);
        float c = expf(v - emax);
        p0 += c * h0; p1 += c * h1v; ws += c;
    }
    s_pool[warp][lane] = p0; s_pool[warp][32 + lane] = p1;
    if (lane == 0) s_ws[warp] = ws;
    __syncthreads();
    if (t < 64) {
        float ps = s_pool[0][t] + s_pool[1][t] + s_pool[2][t] + s_pool[3][t];
        float wtot = s_ws[0] + s_ws[1] + s_ws[2] + s_ws[3];
        s_r[t] = (wtot > 0.f) ? ps / wtot : 0.f;
    }
    __syncthreads();
    if (t < 2) {
        float acc = bias[t];
        for (int d = 0; d < 64; d++)
            acc += g_q[d] * W[d * 2 + t] + s_r[d] * W[(64 + d) * 2 + t];
        outp[b * 2 + t] = acc;
    }
}

// ---------------- launch ----------------
extern "C" void kernel_launch(void* const* d_in, const int* in_sizes, int n_in,
                              void* d_out, int out_size) {
    const float* x          = (const float*)d_in[0];
    const float* edge_attr  = (const float*)d_in[1];
    const int*   edge_index = (const int*)  d_in[2];
    const int*   batch      = (const int*)  d_in[3];
    const int*   stem_idx   = (const int*)  d_in[4];
    const int*   jbond_idx  = (const int*)  d_in[5];
    const float* lin0_w   = (const float*)d_in[6];
    const float* lin0_b   = (const float*)d_in[7];
    const float* net_w1   = (const float*)d_in[8];
    const float* net_b1   = (const float*)d_in[9];
    const float* net_w2   = (const float*)d_in[10];
    const float* net_b2   = (const float*)d_in[11];
    const float* conv_root= (const float*)d_in[12];
    const float* conv_bias= (const float*)d_in[13];
    const float* gru_w_ih = (const float*)d_in[14];
    const float* gru_w_hh = (const float*)d_in[15];
    const float* gru_b_ih = (const float*)d_in[16];
    const float* gru_b_hh = (const float*)d_in[17];
    const float* n2s_w1   = (const float*)d_in[18];
    const float* n2s_b1   = (const float*)d_in[19];
    const float* n2s_w2   = (const float*)d_in[20];
    const float* n2s_b2   = (const float*)d_in[21];
    const float* n2j_w1   = (const float*)d_in[22];
    const float* n2j_b1   = (const float*)d_in[23];
    const float* n2j_w2   = (const float*)d_in[24];
    const float* n2j_b2   = (const float*)d_in[25];
    const float* s2s_b_ih = (const float*)d_in[28];
    const float* s2s_b_hh = (const float*)d_in[29];
    const float* lin_out_w= (const float*)d_in[30];
    const float* lin_out_b= (const float*)d_in[31];
    float* out = (float*)d_out;

    const int* src = edge_index;             // edge_index[0]
    const int* dst = edge_index + N_EDGES;   // edge_index[1]

    cudaFuncSetAttribute(msg_gemm, cudaFuncAttributeMaxDynamicSharedMemorySize,
                         MSG_SMEM_TOTAL);

    zero_deg_kernel<<<N_NODES / 256, 256>>>();
    deg_kernel<<<(N_EDGES + 255) / 256, 256>>>(dst);
    invdeg_kernel<<<N_NODES / 256, 256>>>();
    zero_agg_kernel<<<N_NODES * DIM / 4 / 256, 256>>>();
    lin0_kernel<<<N_NODES * DIM / 256, 256>>>(x, lin0_w, lin0_b);
    h1_kernel<<<N_EDGES * DIM / 256, 256>>>(edge_attr, net_w1, net_b1);
    w2r_kernel<<<(65 * 4096 + 255) / 256, 256>>>(net_w2, net_b2);
    prep_weights_kernel<<<112, 256>>>(conv_root, gru_w_ih, gru_w_hh);

    for (int it = 0; it < 6; it++) {
        msg_gemm<<<N_EDGES / 128, 256, MSG_SMEM_TOTAL>>>(src, dst);
        node_update_tc<<<N_NODES / 64, 256>>>(conv_bias, gru_b_ih, gru_b_hh);
    }

    stem_kernel<<<N_STEMS, 128>>>(stem_idx, n2s_w1, n2s_b1, n2s_w2, n2s_b2, out);
    jbond_kernel<<<N_JBONDS, 128>>>(jbond_idx, n2j_w1, n2j_b1, n2j_w2, n2j_b2, out);
    s2s_q_kernel<<<1, 64>>>(s2s_b_ih, s2s_b_hh);
    pool_kernel<<<N_GRAPHS, 128>>>(batch, lin_out_w, lin_out_b, out);
}